// round 6
// baseline (speedup 1.0000x reference)
#include <cuda_runtime.h>
#include <math.h>

// Problem constants (fixed by setup_inputs)
#define BS_TOK 16384   // B*S
#define DIM    2048    // D
#define NEXP   64      // E
#define HID    1024    // D/2

// Output layout (flattened tuple, fp32):
// idx[BS,2] | scores[BS,2] | probs_soft[BS,64] | importance[64] | load[64]
#define OFF_IDX    0
#define OFF_SCORES (BS_TOK * 2)
#define OFF_PROBS  (BS_TOK * 4)
#define OFF_IMP    (BS_TOK * 4 + BS_TOK * NEXP)
#define OFF_LOAD   (OFF_IMP + NEXP)

// Scratch (device globals: allocation-free)
__device__ float g_mu[BS_TOK];
__device__ float g_rstd[BS_TOK];
__device__ float g_logits[(size_t)BS_TOK * NEXP];   // 4 MB
__device__ float g_h1[(size_t)BS_TOK * HID];        // 67 MB

// ---------------------------------------------------------------------------
// Kernel 1: per-token LayerNorm stats; also zero the atomic accumulators in
// d_out (must happen every launch: graph replays accumulate via atomics).
// ---------------------------------------------------------------------------
__global__ void stats_kernel(const float* __restrict__ x, float* __restrict__ out) {
    const int t   = blockIdx.x;
    const int tid = threadIdx.x;
    const float4* xr = reinterpret_cast<const float4*>(x + (size_t)t * DIM);

    float s = 0.f, sq = 0.f;
    #pragma unroll 2
    for (int i = tid; i < DIM / 4; i += 256) {
        float4 v = xr[i];
        s  += v.x + v.y + v.z + v.w;
        sq += v.x * v.x + v.y * v.y + v.z * v.z + v.w * v.w;
    }
    __shared__ float rs[8], rq[8];
    #pragma unroll
    for (int o = 16; o; o >>= 1) {
        s  += __shfl_down_sync(0xffffffffu, s, o);
        sq += __shfl_down_sync(0xffffffffu, sq, o);
    }
    if ((tid & 31) == 0) { rs[tid >> 5] = s; rq[tid >> 5] = sq; }
    __syncthreads();
    if (tid == 0) {
        float S = 0.f, Q = 0.f;
        #pragma unroll
        for (int i = 0; i < 8; i++) { S += rs[i]; Q += rq[i]; }
        float mu  = S * (1.f / DIM);
        float var = Q * (1.f / DIM) - mu * mu;
        g_mu[t]   = mu;
        g_rstd[t] = rsqrtf(var + 1e-5f);
    }
    if (blockIdx.x == 0 && tid < 2 * NEXP) out[OFF_IMP + tid] = 0.f;
}

// ---------------------------------------------------------------------------
// Generic fp32 register-tiled GEMM:  C[M,N] = op(A)[M,K] * B[N,K]^T
// A,B are K-contiguous (row-major). Optional fused LayerNorm on A and exact
// GELU epilogue. DEST selects the device-global output buffer.
// ---------------------------------------------------------------------------
template <int BM, int BN, int BK, int TM, int TN, bool LN, bool GELU, int DEST>
__global__ void __launch_bounds__((BM / TM) * (BN / TN))
gemm_kernel(const float* __restrict__ A, const float* __restrict__ B,
            int M, int N, int K,
            const float* __restrict__ gamma, const float* __restrict__ beta) {
    constexpr int NT = (BM / TM) * (BN / TN);
    __shared__ float As[BK][BM + 4];
    __shared__ float Bs[BK][BN + 4];
    __shared__ float s_mu[BM], s_rstd[BM];

    const int bm  = blockIdx.y * BM;
    const int bn  = blockIdx.x * BN;
    const int tid = threadIdx.x;
    const int tcol = tid % (BN / TN);
    const int trow = tid / (BN / TN);

    if (LN) {
        for (int i = tid; i < BM; i += NT) {
            s_mu[i]   = g_mu[bm + i];
            s_rstd[i] = g_rstd[bm + i];
        }
    }

    float acc[TM][TN];
    #pragma unroll
    for (int i = 0; i < TM; i++)
        #pragma unroll
        for (int j = 0; j < TN; j++) acc[i][j] = 0.f;

    for (int k0 = 0; k0 < K; k0 += BK) {
        __syncthreads();
        // Load A tile (transposed into smem), fused LN if requested.
        #pragma unroll
        for (int idx = tid * 4; idx < BM * BK; idx += NT * 4) {
            int r = idx / BK, c = idx % BK;
            float4 v = *reinterpret_cast<const float4*>(&A[(size_t)(bm + r) * K + k0 + c]);
            if (LN) {
                float m = s_mu[r], rs = s_rstd[r];
                v.x = (v.x - m) * rs * gamma[k0 + c + 0] + beta[k0 + c + 0];
                v.y = (v.y - m) * rs * gamma[k0 + c + 1] + beta[k0 + c + 1];
                v.z = (v.z - m) * rs * gamma[k0 + c + 2] + beta[k0 + c + 2];
                v.w = (v.w - m) * rs * gamma[k0 + c + 3] + beta[k0 + c + 3];
            }
            As[c + 0][r] = v.x; As[c + 1][r] = v.y;
            As[c + 2][r] = v.z; As[c + 3][r] = v.w;
        }
        // Load B tile (transposed into smem).
        #pragma unroll
        for (int idx = tid * 4; idx < BN * BK; idx += NT * 4) {
            int r = idx / BK, c = idx % BK;
            float4 v = *reinterpret_cast<const float4*>(&B[(size_t)(bn + r) * K + k0 + c]);
            Bs[c + 0][r] = v.x; Bs[c + 1][r] = v.y;
            Bs[c + 2][r] = v.z; Bs[c + 3][r] = v.w;
        }
        __syncthreads();

        #pragma unroll
        for (int k = 0; k < BK; k++) {
            float rm[TM], rn[TN];
            #pragma unroll
            for (int i = 0; i < TM; i += 4) {
                float4 v = *reinterpret_cast<const float4*>(&As[k][trow * TM + i]);
                rm[i] = v.x; rm[i + 1] = v.y; rm[i + 2] = v.z; rm[i + 3] = v.w;
            }
            #pragma unroll
            for (int j = 0; j < TN; j += 4) {
                float4 v = *reinterpret_cast<const float4*>(&Bs[k][tcol * TN + j]);
                rn[j] = v.x; rn[j + 1] = v.y; rn[j + 2] = v.z; rn[j + 3] = v.w;
            }
            #pragma unroll
            for (int i = 0; i < TM; i++)
                #pragma unroll
                for (int j = 0; j < TN; j++) acc[i][j] = fmaf(rm[i], rn[j], acc[i][j]);
        }
    }

    float* __restrict__ C = (DEST == 0) ? g_logits : g_h1;
    #pragma unroll
    for (int i = 0; i < TM; i++) {
        int row = bm + trow * TM + i;
        #pragma unroll
        for (int j = 0; j < TN; j++) {
            int col = bn + tcol * TN + j;
            float v = acc[i][j];
            if (GELU) v = 0.5f * v * (1.f + erff(v * 0.70710678118654752f));
            C[(size_t)row * N + col] = v;
        }
    }
}

// ---------------------------------------------------------------------------
// Kernel 4: per-token epilogue.
//   z = h1 . W2 ; diff = sigmoid(z) ; l = logits/(1+diff)
//   softmax, top-2 (ties -> lowest index, matching lax.top_k), score norm,
//   importance/load accumulation.
// ---------------------------------------------------------------------------
__global__ void epilogue_kernel(const float* __restrict__ W2, float* __restrict__ out) {
    const int t   = blockIdx.x;
    const int tid = threadIdx.x;  // 256 threads

    // z = dot(h1[t], W2)
    const float4* h4 = reinterpret_cast<const float4*>(g_h1 + (size_t)t * HID);
    const float4* w4 = reinterpret_cast<const float4*>(W2);
    float z = 0.f;
    #pragma unroll
    for (int i = tid; i < HID / 4; i += 256) {
        float4 a = h4[i], b = w4[i];
        z += a.x * b.x + a.y * b.y + a.z * b.z + a.w * b.w;
    }
    __shared__ float red[8];
    #pragma unroll
    for (int o = 16; o; o >>= 1) z += __shfl_down_sync(0xffffffffu, z, o);
    if ((tid & 31) == 0) red[tid >> 5] = z;
    __syncthreads();

    __shared__ float s_inv;
    __shared__ float sl[NEXP];
    __shared__ float sp[NEXP];
    if (tid == 0) {
        float Z = 0.f;
        #pragma unroll
        for (int i = 0; i < 8; i++) Z += red[i];
        float diff = 1.f / (1.f + expf(-Z));   // sigmoid
        s_inv = 1.f / (1.f + diff);            // TEMP = 1
    }
    __syncthreads();

    if (tid < NEXP) sl[tid] = g_logits[(size_t)t * NEXP + tid] * s_inv;
    __syncthreads();

    // Softmax over 64 experts in warp 0 (2 experts per lane).
    if (tid < 32) {
        float l0 = sl[tid], l1 = sl[tid + 32];
        float m = fmaxf(l0, l1);
        #pragma unroll
        for (int o = 16; o; o >>= 1) m = fmaxf(m, __shfl_xor_sync(0xffffffffu, m, o));
        float e0 = expf(l0 - m), e1 = expf(l1 - m);
        float s = e0 + e1;
        #pragma unroll
        for (int o = 16; o; o >>= 1) s += __shfl_xor_sync(0xffffffffu, s, o);
        float inv = 1.f / s;
        float p0 = e0 * inv, p1 = e1 * inv;
        sp[tid] = p0; sp[tid + 32] = p1;
        out[OFF_PROBS + (size_t)t * NEXP + tid]      = p0;
        out[OFF_PROBS + (size_t)t * NEXP + tid + 32] = p1;
        atomicAdd(&out[OFF_IMP + tid],      p0 * (1.f / BS_TOK));
        atomicAdd(&out[OFF_IMP + tid + 32], p1 * (1.f / BS_TOK));
    }
    __syncthreads();

    if (tid == 0) {
        int i0 = 0; float b0 = sl[0];
        #pragma unroll
        for (int e = 1; e < NEXP; e++) if (sl[e] > b0) { b0 = sl[e]; i0 = e; }
        int i1 = -1; float b1 = -3.4e38f;
        #pragma unroll
        for (int e = 0; e < NEXP; e++) if (e != i0 && sl[e] > b1) { b1 = sl[e]; i1 = e; }

        // straight-through: probs_st = (hard - p) + p ; gather at idx
        float s0 = (1.f - sp[i0]) + sp[i0];
        float s1 = (1.f - sp[i1]) + sp[i1];
        float ssum = fmaxf(s0 + s1, 1e-9f);
        out[OFF_IDX + t * 2 + 0]    = (float)i0;
        out[OFF_IDX + t * 2 + 1]    = (float)i1;
        out[OFF_SCORES + t * 2 + 0] = s0 / ssum;
        out[OFF_SCORES + t * 2 + 1] = s1 / ssum;
        atomicAdd(&out[OFF_LOAD + i0], 1.f / BS_TOK);
        atomicAdd(&out[OFF_LOAD + i1], 1.f / BS_TOK);
    }
}

// ---------------------------------------------------------------------------
// kernel_launch: graph-capturable sequence of 4 kernels.
// Inputs (metadata order): x[B,S,D], Wg[E,D], gamma[D], beta[D],
//                          W1[H,D], W2[1,H]  — all float32.
// ---------------------------------------------------------------------------
extern "C" void kernel_launch(void* const* d_in, const int* in_sizes, int n_in,
                              void* d_out, int out_size) {
    const float* x     = (const float*)d_in[0];
    const float* Wg    = (const float*)d_in[1];
    const float* gamma = (const float*)d_in[2];
    const float* beta  = (const float*)d_in[3];
    const float* W1    = (const float*)d_in[4];
    const float* W2    = (const float*)d_in[5];
    float* out = (float*)d_out;

    // 1) LN stats + zero importance/load accumulators
    stats_kernel<<<BS_TOK, 256>>>(x, out);

    // 2) logits = x @ Wg^T  (fp32; top-k stability requires full precision)
    {
        constexpr int BM = 128, BN = 64, BK = 16, TM = 8, TN = 4;
        dim3 grid(NEXP / BN, BS_TOK / BM);
        gemm_kernel<BM, BN, BK, TM, TN, false, false, 0>
            <<<grid, (BM / TM) * (BN / TN)>>>(x, Wg, BS_TOK, NEXP, DIM, nullptr, nullptr);
    }

    // 3) h1 = gelu(LN(x) @ W1^T)  (fused LN + exact-erf GELU epilogue)
    {
        constexpr int BM = 128, BN = 128, BK = 16, TM = 8, TN = 8;
        dim3 grid(HID / BN, BS_TOK / BM);
        gemm_kernel<BM, BN, BK, TM, TN, true, true, 1>
            <<<grid, (BM / TM) * (BN / TN)>>>(x, W1, BS_TOK, HID, DIM, gamma, beta);
    }

    // 4) diff / modulate / softmax / top-2 / outputs
    epilogue_kernel<<<BS_TOK, 256>>>(W2, out);

    (void)in_sizes; (void)n_in; (void)out_size;
}

// round 8
// speedup vs baseline: 6.7847x; 6.7847x over previous
#include <cuda_runtime.h>
#include <cuda_bf16.h>
#include <math.h>
#include <stdint.h>

// Problem constants (fixed by setup_inputs)
#define BS_TOK 16384   // B*S
#define DIM    2048    // D
#define NEXP   64      // E
#define HID    1024    // D/2
#define NXT    (HID / 128)   // 8 N-tiles in the h1 GEMM

// Output layout (flattened tuple, fp32):
// idx[BS,2] | scores[BS,2] | probs_soft[BS,64] | importance[64] | load[64]
#define OFF_IDX    0
#define OFF_SCORES (BS_TOK * 2)
#define OFF_PROBS  (BS_TOK * 4)
#define OFF_IMP    (BS_TOK * 4 + BS_TOK * NEXP)
#define OFF_LOAD   (OFF_IMP + NEXP)

// Scratch (device globals: allocation-free)
__device__ __nv_bfloat16 g_xbf[(size_t)BS_TOK * DIM];   // LN(x) in bf16, 64 MB
__device__ __nv_bfloat16 g_w1bf[(size_t)HID * DIM];     // W1 in bf16, 4 MB
__device__ float g_logits[(size_t)BS_TOK * NEXP];       // 4 MB
__device__ float g_zpart[NXT][BS_TOK];                  // partial h1.W2 dots

// ---------------------------------------------------------------------------
// PTX helpers — family-portable only (no tcgen05: ptxas targets sm_103 base)
// ---------------------------------------------------------------------------
__device__ __forceinline__ uint32_t smem_u32(const void* p) {
    uint32_t a;
    asm("{ .reg .u64 t; cvta.to.shared.u64 t, %1; cvt.u32.u64 %0, t; }" : "=r"(a) : "l"(p));
    return a;
}
#define SWZ(o) ((o) ^ (((o) >> 3) & 0x70))
#define CP_ASYNC16(dst, src) \
    asm volatile("cp.async.cg.shared.global [%0], [%1], 16;" :: "r"(dst), "l"(src))
#define CP_COMMIT() asm volatile("cp.async.commit_group;" ::: "memory")
#define CP_WAIT1()  asm volatile("cp.async.wait_group 1;" ::: "memory")
#define CP_WAIT0()  asm volatile("cp.async.wait_group 0;" ::: "memory")

__device__ __forceinline__ void ldsm4(uint32_t* r, uint32_t addr) {
    asm volatile("ldmatrix.sync.aligned.m8n8.x4.shared.b16 {%0,%1,%2,%3}, [%4];"
                 : "=r"(r[0]), "=r"(r[1]), "=r"(r[2]), "=r"(r[3]) : "r"(addr));
}
__device__ __forceinline__ void mma16816(float* c, const uint32_t* a, const uint32_t* b) {
    asm volatile(
        "mma.sync.aligned.m16n8k16.row.col.f32.bf16.bf16.f32 "
        "{%0,%1,%2,%3}, {%4,%5,%6,%7}, {%8,%9}, {%0,%1,%2,%3};"
        : "+f"(c[0]), "+f"(c[1]), "+f"(c[2]), "+f"(c[3])
        : "r"(a[0]), "r"(a[1]), "r"(a[2]), "r"(a[3]), "r"(b[0]), "r"(b[1]));
}

// ---------------------------------------------------------------------------
// Kernel 1: LN stats + normalize + bf16 convert (writes g_xbf); zeroes the
// importance/load accumulators in d_out (required every replay).
// ---------------------------------------------------------------------------
__global__ void __launch_bounds__(256) prep_kernel(
    const float* __restrict__ x, const float* __restrict__ gamma,
    const float* __restrict__ beta, float* __restrict__ out) {
    const int t = blockIdx.x, tid = threadIdx.x;
    const float4* xr = reinterpret_cast<const float4*>(x + (size_t)t * DIM);

    float s = 0.f, sq = 0.f;
    #pragma unroll 2
    for (int i = tid; i < DIM / 4; i += 256) {
        float4 v = xr[i];
        s  += v.x + v.y + v.z + v.w;
        sq += v.x * v.x + v.y * v.y + v.z * v.z + v.w * v.w;
    }
    __shared__ float rs_[8], rq_[8];
    #pragma unroll
    for (int o = 16; o; o >>= 1) {
        s  += __shfl_down_sync(0xffffffffu, s, o);
        sq += __shfl_down_sync(0xffffffffu, sq, o);
    }
    if ((tid & 31) == 0) { rs_[tid >> 5] = s; rq_[tid >> 5] = sq; }
    __syncthreads();
    __shared__ float s_mu, s_rstd;
    if (tid == 0) {
        float S = 0.f, Q = 0.f;
        #pragma unroll
        for (int i = 0; i < 8; i++) { S += rs_[i]; Q += rq_[i]; }
        float mu  = S * (1.f / DIM);
        float var = Q * (1.f / DIM) - mu * mu;
        s_mu = mu; s_rstd = rsqrtf(var + 1e-5f);
    }
    __syncthreads();
    const float mu = s_mu, rstd = s_rstd;
    const float4* gr = reinterpret_cast<const float4*>(gamma);
    const float4* br = reinterpret_cast<const float4*>(beta);
    uint2* dst = reinterpret_cast<uint2*>(g_xbf + (size_t)t * DIM);
    for (int i = tid; i < DIM / 4; i += 256) {
        float4 v = xr[i], g = gr[i], b = br[i];
        float h0 = (v.x - mu) * rstd * g.x + b.x;
        float h1 = (v.y - mu) * rstd * g.y + b.y;
        float h2 = (v.z - mu) * rstd * g.z + b.z;
        float h3 = (v.w - mu) * rstd * g.w + b.w;
        __nv_bfloat162 pa = __floats2bfloat162_rn(h0, h1);
        __nv_bfloat162 pb = __floats2bfloat162_rn(h2, h3);
        uint2 u;
        u.x = *reinterpret_cast<unsigned int*>(&pa);
        u.y = *reinterpret_cast<unsigned int*>(&pb);
        dst[i] = u;
    }
    if (blockIdx.x == 0 && tid < 2 * NEXP) out[OFF_IMP + tid] = 0.f;
}

// ---------------------------------------------------------------------------
// Kernel 2: W1 fp32 -> bf16 (4 elems/thread)
// ---------------------------------------------------------------------------
__global__ void __launch_bounds__(256) w1conv_kernel(const float* __restrict__ W1) {
    size_t i = (size_t)blockIdx.x * 256 + threadIdx.x;
    float4 v = reinterpret_cast<const float4*>(W1)[i];
    __nv_bfloat162 pa = __floats2bfloat162_rn(v.x, v.y);
    __nv_bfloat162 pb = __floats2bfloat162_rn(v.z, v.w);
    uint2 u;
    u.x = *reinterpret_cast<unsigned int*>(&pa);
    u.y = *reinterpret_cast<unsigned int*>(&pb);
    reinterpret_cast<uint2*>(g_w1bf)[i] = u;
}

// ---------------------------------------------------------------------------
// Kernel 3: logits = x @ Wg^T in full fp32 (mandatory for top-2 stability).
// Register-tiled SIMT GEMM: BM=128, BN=64, BK=16, TM=8, TN=4 (verified R6).
// ---------------------------------------------------------------------------
__global__ void __launch_bounds__(256) logits_kernel(
    const float* __restrict__ A, const float* __restrict__ B) {
    __shared__ float As[16][132];
    __shared__ float Bs[16][68];
    const int bm = blockIdx.y * 128, bn = blockIdx.x * 64;
    const int tid = threadIdx.x;
    const int tcol = tid % 16, trow = tid / 16;

    float acc[8][4];
    #pragma unroll
    for (int i = 0; i < 8; i++)
        #pragma unroll
        for (int j = 0; j < 4; j++) acc[i][j] = 0.f;

    for (int k0 = 0; k0 < DIM; k0 += 16) {
        __syncthreads();
        #pragma unroll
        for (int idx = tid * 4; idx < 128 * 16; idx += 256 * 4) {
            int r = idx / 16, c = idx % 16;
            float4 v = *reinterpret_cast<const float4*>(&A[(size_t)(bm + r) * DIM + k0 + c]);
            As[c + 0][r] = v.x; As[c + 1][r] = v.y; As[c + 2][r] = v.z; As[c + 3][r] = v.w;
        }
        #pragma unroll
        for (int idx = tid * 4; idx < 64 * 16; idx += 256 * 4) {
            int r = idx / 16, c = idx % 16;
            float4 v = *reinterpret_cast<const float4*>(&B[(size_t)(bn + r) * DIM + k0 + c]);
            Bs[c + 0][r] = v.x; Bs[c + 1][r] = v.y; Bs[c + 2][r] = v.z; Bs[c + 3][r] = v.w;
        }
        __syncthreads();
        #pragma unroll
        for (int k = 0; k < 16; k++) {
            float rm[8], rn[4];
            #pragma unroll
            for (int i = 0; i < 8; i += 4) {
                float4 v = *reinterpret_cast<const float4*>(&As[k][trow * 8 + i]);
                rm[i] = v.x; rm[i + 1] = v.y; rm[i + 2] = v.z; rm[i + 3] = v.w;
            }
            {
                float4 v = *reinterpret_cast<const float4*>(&Bs[k][tcol * 4]);
                rn[0] = v.x; rn[1] = v.y; rn[2] = v.z; rn[3] = v.w;
            }
            #pragma unroll
            for (int i = 0; i < 8; i++)
                #pragma unroll
                for (int j = 0; j < 4; j++) acc[i][j] = fmaf(rm[i], rn[j], acc[i][j]);
        }
    }
    #pragma unroll
    for (int i = 0; i < 8; i++) {
        int row = bm + trow * 8 + i;
        #pragma unroll
        for (int j = 0; j < 4; j++)
            g_logits[(size_t)row * NEXP + bn + tcol * 4 + j] = acc[i][j];
    }
}

// ---------------------------------------------------------------------------
// Kernel 4: bf16 mma.sync GEMM h1 = LN(x)@W1^T, CTA tile 128x128, BK=64,
// cp.async double-buffered, SW128-swizzled smem, fused GELU + W2-dot
// epilogue. Writes partial z sums to g_zpart[blockIdx.x][token].
// 8 warps: warp_m = wid>>2 (64 rows), warp_n = wid&3 (32 cols).
// ---------------------------------------------------------------------------
__device__ __forceinline__ void copy_tiles(uint32_t sa, uint32_t sb,
                                           const char* ag, const char* bg, int tid) {
    #pragma unroll
    for (int t = 0; t < 4; t++) {
        int u = tid + t * 256;            // 0..1023 16B units
        int row = u >> 3, cu = u & 7;     // 128 rows x 8 units (64 bf16 = 128B)
        size_t goff = (size_t)row * (DIM * 2) + (size_t)cu * 16;
        uint32_t soff = SWZ(row * 128 + cu * 16);
        CP_ASYNC16(sa + soff, ag + goff);
        CP_ASYNC16(sb + soff, bg + goff);
    }
}

__device__ __forceinline__ void compute_chunk(uint32_t abase, uint32_t bbase,
                                              int warp_m, int warp_n, int lane,
                                              float acc[4][4][4]) {
    #pragma unroll
    for (int ks = 0; ks < 4; ks++) {
        uint32_t ra[4][4];
        #pragma unroll
        for (int a = 0; a < 4; a++) {
            int row = warp_m * 64 + a * 16 + (lane & 15);
            int bc  = ks * 32 + (((lane >> 4) & 1) << 4);
            ldsm4(ra[a], abase + SWZ(row * 128 + bc));
        }
        uint32_t rb[4][2];
        #pragma unroll
        for (int bb = 0; bb < 4; bb += 2) {
            int nrow = warp_n * 32 + bb * 8 + (lane & 7) + ((lane >> 4) & 1) * 8;
            int kc   = ks * 32 + (((lane >> 3) & 1) << 4);
            uint32_t r[4];
            ldsm4(r, bbase + SWZ(nrow * 128 + kc));
            rb[bb][0] = r[0];     rb[bb][1] = r[1];
            rb[bb + 1][0] = r[2]; rb[bb + 1][1] = r[3];
        }
        #pragma unroll
        for (int a = 0; a < 4; a++)
            #pragma unroll
            for (int b = 0; b < 4; b++)
                mma16816(acc[a][b], ra[a], rb[b]);
    }
}

__global__ void __launch_bounds__(256, 1) h1z_kernel(const float* __restrict__ W2) {
    extern __shared__ char dynsmem[];
    const uint32_t raw  = smem_u32(dynsmem);
    const uint32_t base = (raw + 1023u) & ~1023u;
    char* sm = dynsmem + (base - raw);
    const int OA0 = 0, OA1 = 16384, OB0 = 32768, OB1 = 49152;
    const int OW2 = 65536, OZ = 66048;

    const int tid = threadIdx.x, wid = tid >> 5, lane = tid & 31;
    const int warp_m = wid >> 2, warp_n = wid & 3;
    const int bn = blockIdx.x * 128;   // HID tile
    const int bm = blockIdx.y * 128;   // token tile

    float* w2s  = reinterpret_cast<float*>(sm + OW2);
    float* zrow = reinterpret_cast<float*>(sm + OZ);
    if (tid < 128) { w2s[tid] = W2[bn + tid]; zrow[tid] = 0.f; }

    const char* ag = reinterpret_cast<const char*>(g_xbf + (size_t)bm * DIM);
    const char* bg = reinterpret_cast<const char*>(g_w1bf + (size_t)bn * DIM);

    copy_tiles(base + OA0, base + OB0, ag, bg, tid);
    CP_COMMIT();

    float acc[4][4][4];
    #pragma unroll
    for (int a = 0; a < 4; a++)
        #pragma unroll
        for (int b = 0; b < 4; b++)
            #pragma unroll
            for (int c = 0; c < 4; c++) acc[a][b][c] = 0.f;

    #pragma unroll 1
    for (int i = 0; i < 32; i++) {
        if (i < 31) {
            const int nb = (i + 1) & 1;
            copy_tiles(base + (nb ? OA1 : OA0), base + (nb ? OB1 : OB0),
                       ag + (size_t)(i + 1) * 128, bg + (size_t)(i + 1) * 128, tid);
            CP_COMMIT();
            CP_WAIT1();
        } else {
            CP_WAIT0();
        }
        __syncthreads();
        const int cb = i & 1;
        compute_chunk(base + (cb ? OA1 : OA0), base + (cb ? OB1 : OB0),
                      warp_m, warp_n, lane, acc);
        __syncthreads();
    }

    // Fused epilogue: GELU + dot with W2, row-reduce.
    // acc[a][b] layout: c0:(r=lane/4, col=2*(lane%4)) c1:(r, col+1)
    //                   c2:(r+8, col) c3:(r+8, col+1)
    float z[8];
    #pragma unroll
    for (int j = 0; j < 8; j++) z[j] = 0.f;
    #pragma unroll
    for (int a = 0; a < 4; a++) {
        #pragma unroll
        for (int b = 0; b < 4; b++) {
            const int colb = warp_n * 32 + b * 8 + 2 * (lane & 3);
            const float w0 = w2s[colb], w1 = w2s[colb + 1];
            float v0 = acc[a][b][0], v1 = acc[a][b][1];
            float v2 = acc[a][b][2], v3 = acc[a][b][3];
            v0 = 0.5f * v0 * (1.f + erff(v0 * 0.70710678118654752f));
            v1 = 0.5f * v1 * (1.f + erff(v1 * 0.70710678118654752f));
            v2 = 0.5f * v2 * (1.f + erff(v2 * 0.70710678118654752f));
            v3 = 0.5f * v3 * (1.f + erff(v3 * 0.70710678118654752f));
            z[a * 2 + 0] += v0 * w0 + v1 * w1;
            z[a * 2 + 1] += v2 * w0 + v3 * w1;
        }
    }
    // reduce over the 4 lanes sharing each row (lanes differ in bits 0..1)
    #pragma unroll
    for (int m = 1; m <= 2; m <<= 1)
        #pragma unroll
        for (int j = 0; j < 8; j++)
            z[j] += __shfl_xor_sync(0xffffffffu, z[j], m);
    if ((lane & 3) == 0) {
        #pragma unroll
        for (int a = 0; a < 4; a++) {
            const int r0 = warp_m * 64 + a * 16 + (lane >> 2);
            atomicAdd(&zrow[r0], z[a * 2 + 0]);
            atomicAdd(&zrow[r0 + 8], z[a * 2 + 1]);
        }
    }
    __syncthreads();
    if (tid < 128) g_zpart[blockIdx.x][bm + tid] = zrow[tid];
}

// ---------------------------------------------------------------------------
// Kernel 5: warp-per-token epilogue. z-sum -> sigmoid -> modulate -> softmax
// -> top-2 (ties: lowest index, matching lax.top_k) -> outputs. Importance /
// load aggregated in smem, one global atomic per expert per block.
// ---------------------------------------------------------------------------
__global__ void __launch_bounds__(256) epilogue_kernel(float* __restrict__ out) {
    __shared__ float s_imp[NEXP], s_load[NEXP];
    const int tid = threadIdx.x;
    if (tid < NEXP) s_imp[tid] = 0.f;
    else if (tid < 2 * NEXP) s_load[tid - NEXP] = 0.f;
    __syncthreads();

    const int w = tid >> 5, lane = tid & 31;
    const int t = blockIdx.x * 8 + w;

    float zp = (lane < NXT) ? g_zpart[lane][t] : 0.f;
    #pragma unroll
    for (int o = 16; o; o >>= 1) zp += __shfl_xor_sync(0xffffffffu, zp, o);
    const float sc = 1.f / (1.f + 1.f / (1.f + expf(-zp)));   // 1/(1+sigmoid(z))

    const float* lrow = g_logits + (size_t)t * NEXP;
    const float l0 = lrow[lane] * sc;
    const float l1 = lrow[lane + 32] * sc;

    float m = fmaxf(l0, l1);
    #pragma unroll
    for (int o = 16; o; o >>= 1) m = fmaxf(m, __shfl_xor_sync(0xffffffffu, m, o));
    const float e0 = expf(l0 - m), e1 = expf(l1 - m);
    float se = e0 + e1;
    #pragma unroll
    for (int o = 16; o; o >>= 1) se += __shfl_xor_sync(0xffffffffu, se, o);
    const float inv = 1.f / se;
    const float p0 = e0 * inv, p1 = e1 * inv;

    out[OFF_PROBS + (size_t)t * NEXP + lane]      = p0;
    out[OFF_PROBS + (size_t)t * NEXP + lane + 32] = p1;
    atomicAdd(&s_imp[lane], p0);
    atomicAdd(&s_imp[lane + 32], p1);

    // top-1 (tie -> lower index)
    float v; int ei;
    if (l1 > l0) { v = l1; ei = lane + 32; } else { v = l0; ei = lane; }
    #pragma unroll
    for (int o = 16; o; o >>= 1) {
        float ov = __shfl_xor_sync(0xffffffffu, v, o);
        int   oi = __shfl_xor_sync(0xffffffffu, ei, o);
        if (ov > v || (ov == v && oi < ei)) { v = ov; ei = oi; }
    }
    const int i0 = ei;
    // top-2: exclude i0
    float a0 = (lane == i0)      ? -3.4e38f : l0;
    float a1 = (lane + 32 == i0) ? -3.4e38f : l1;
    if (a1 > a0) { v = a1; ei = lane + 32; } else { v = a0; ei = lane; }
    #pragma unroll
    for (int o = 16; o; o >>= 1) {
        float ov = __shfl_xor_sync(0xffffffffu, v, o);
        int   oi = __shfl_xor_sync(0xffffffffu, ei, o);
        if (ov > v || (ov == v && oi < ei)) { v = ov; ei = oi; }
    }
    const int i1 = ei;

    const float c0 = (i0 < 32) ? p0 : p1;
    const float pi0 = __shfl_sync(0xffffffffu, c0, i0 & 31);
    const float c1 = (i1 < 32) ? p0 : p1;
    const float pi1 = __shfl_sync(0xffffffffu, c1, i1 & 31);

    if (lane == 0) {
        const float s0 = (1.0f - pi0) + pi0;   // straight-through, faithful to ref
        const float s1 = (1.0f - pi1) + pi1;
        const float sn = fmaxf(s0 + s1, 1e-9f);
        out[OFF_IDX + t * 2 + 0]    = (float)i0;
        out[OFF_IDX + t * 2 + 1]    = (float)i1;
        out[OFF_SCORES + t * 2 + 0] = s0 / sn;
        out[OFF_SCORES + t * 2 + 1] = s1 / sn;
        atomicAdd(&s_load[i0], 1.f);
        atomicAdd(&s_load[i1], 1.f);
    }
    __syncthreads();
    if (tid < NEXP)
        atomicAdd(&out[OFF_IMP + tid], s_imp[tid] * (1.f / BS_TOK));
    else if (tid < 2 * NEXP)
        atomicAdd(&out[OFF_LOAD + tid - NEXP], s_load[tid - NEXP] * (1.f / BS_TOK));
}

// ---------------------------------------------------------------------------
// kernel_launch: graph-capturable sequence of 5 kernels.
// Inputs: x[B,S,D], Wg[E,D], gamma[D], beta[D], W1[H,D], W2[1,H] (fp32)
// ---------------------------------------------------------------------------
extern "C" void kernel_launch(void* const* d_in, const int* in_sizes, int n_in,
                              void* d_out, int out_size) {
    const float* x     = (const float*)d_in[0];
    const float* Wg    = (const float*)d_in[1];
    const float* gamma = (const float*)d_in[2];
    const float* beta  = (const float*)d_in[3];
    const float* W1    = (const float*)d_in[4];
    const float* W2    = (const float*)d_in[5];
    float* out = (float*)d_out;

    cudaFuncSetAttribute(h1z_kernel, cudaFuncAttributeMaxDynamicSharedMemorySize, 67584);

    // 1) LN + bf16 convert + zero accumulators
    prep_kernel<<<BS_TOK, 256>>>(x, gamma, beta, out);
    // 2) W1 -> bf16
    w1conv_kernel<<<(HID * DIM / 4) / 256, 256>>>(W1);
    // 3) logits fp32 (top-2 stability)
    logits_kernel<<<dim3(1, BS_TOK / 128), 256>>>(x, Wg);
    // 4) bf16 mma.sync h1 GEMM + fused GELU/W2-dot
    h1z_kernel<<<dim3(NXT, BS_TOK / 128), 256, 67584>>>(W2);
    // 5) softmax / top-2 / outputs
    epilogue_kernel<<<BS_TOK / 8, 256>>>(out);

    (void)in_sizes; (void)n_in; (void)out_size;
}

// round 9
// speedup vs baseline: 9.0823x; 1.3386x over previous
#include <cuda_runtime.h>
#include <cuda_bf16.h>
#include <cuda_fp16.h>
#include <math.h>
#include <stdint.h>

// Problem constants (fixed by setup_inputs)
#define BS_TOK 16384   // B*S
#define DIM    2048    // D
#define NEXP   64      // E
#define HID    1024    // D/2
#define NXT    (HID / 128)   // 8 N-tiles in the h1 GEMM

// Output layout (flattened tuple, fp32):
// idx[BS,2] | scores[BS,2] | probs_soft[BS,64] | importance[64] | load[64]
#define OFF_IDX    0
#define OFF_SCORES (BS_TOK * 2)
#define OFF_PROBS  (BS_TOK * 4)
#define OFF_IMP    (BS_TOK * 4 + BS_TOK * NEXP)
#define OFF_LOAD   (OFF_IMP + NEXP)

// Scratch (device globals: allocation-free)
__device__ __nv_bfloat16 g_xbf[(size_t)BS_TOK * DIM];   // LN(x) bf16, 64 MB
__device__ __half g_xhi[(size_t)BS_TOK * DIM];          // 1024*x hi fp16
__device__ __half g_xlo[(size_t)BS_TOK * DIM];          // 1024*x lo fp16
__device__ __nv_bfloat16 g_w1bf[(size_t)HID * DIM];     // W1 bf16
__device__ __half g_wghi[(size_t)NEXP * DIM];           // 1024*Wg hi fp16
__device__ __half g_wglo[(size_t)NEXP * DIM];           // 1024*Wg lo fp16
__device__ float g_logits[(size_t)BS_TOK * NEXP];
__device__ float g_zpart[NXT][BS_TOK];

// ---------------------------------------------------------------------------
// PTX helpers — family-portable only (no tcgen05: ptxas targets sm_103 base)
// ---------------------------------------------------------------------------
__device__ __forceinline__ uint32_t smem_u32(const void* p) {
    uint32_t a;
    asm("{ .reg .u64 t; cvta.to.shared.u64 t, %1; cvt.u32.u64 %0, t; }" : "=r"(a) : "l"(p));
    return a;
}
#define SWZ(o) ((o) ^ (((o) >> 3) & 0x70))
#define CP_ASYNC16(dst, src) \
    asm volatile("cp.async.cg.shared.global [%0], [%1], 16;" :: "r"(dst), "l"(src))
#define CP_COMMIT() asm volatile("cp.async.commit_group;" ::: "memory")
#define CP_WAIT1()  asm volatile("cp.async.wait_group 1;" ::: "memory")
#define CP_WAIT0()  asm volatile("cp.async.wait_group 0;" ::: "memory")

__device__ __forceinline__ void ldsm4(uint32_t* r, uint32_t addr) {
    asm volatile("ldmatrix.sync.aligned.m8n8.x4.shared.b16 {%0,%1,%2,%3}, [%4];"
                 : "=r"(r[0]), "=r"(r[1]), "=r"(r[2]), "=r"(r[3]) : "r"(addr));
}
__device__ __forceinline__ void mma_bf16(float* c, const uint32_t* a, const uint32_t* b) {
    asm volatile(
        "mma.sync.aligned.m16n8k16.row.col.f32.bf16.bf16.f32 "
        "{%0,%1,%2,%3}, {%4,%5,%6,%7}, {%8,%9}, {%0,%1,%2,%3};"
        : "+f"(c[0]), "+f"(c[1]), "+f"(c[2]), "+f"(c[3])
        : "r"(a[0]), "r"(a[1]), "r"(a[2]), "r"(a[3]), "r"(b[0]), "r"(b[1]));
}
__device__ __forceinline__ void mma_f16(float* c, const uint32_t* a, const uint32_t* b) {
    asm volatile(
        "mma.sync.aligned.m16n8k16.row.col.f32.f16.f16.f32 "
        "{%0,%1,%2,%3}, {%4,%5,%6,%7}, {%8,%9}, {%0,%1,%2,%3};"
        : "+f"(c[0]), "+f"(c[1]), "+f"(c[2]), "+f"(c[3])
        : "r"(a[0]), "r"(a[1]), "r"(a[2]), "r"(a[3]), "r"(b[0]), "r"(b[1]));
}

// ---------------------------------------------------------------------------
// Kernel 1: LN stats + bf16 LN(x) + fp16 hi/lo split of 1024*x (for logits
// MMA); zeroes importance/load accumulators (required every graph replay).
// ---------------------------------------------------------------------------
__global__ void __launch_bounds__(256) prep_kernel(
    const float* __restrict__ x, const float* __restrict__ gamma,
    const float* __restrict__ beta, float* __restrict__ out) {
    const int t = blockIdx.x, tid = threadIdx.x;
    const float4* xr = reinterpret_cast<const float4*>(x + (size_t)t * DIM);

    float4 v[2];
    v[0] = xr[tid];
    v[1] = xr[tid + 256];

    float s = 0.f, sq = 0.f;
    #pragma unroll
    for (int j = 0; j < 2; j++) {
        s  += v[j].x + v[j].y + v[j].z + v[j].w;
        sq += v[j].x * v[j].x + v[j].y * v[j].y + v[j].z * v[j].z + v[j].w * v[j].w;
    }
    __shared__ float rs_[8], rq_[8];
    #pragma unroll
    for (int o = 16; o; o >>= 1) {
        s  += __shfl_down_sync(0xffffffffu, s, o);
        sq += __shfl_down_sync(0xffffffffu, sq, o);
    }
    if ((tid & 31) == 0) { rs_[tid >> 5] = s; rq_[tid >> 5] = sq; }
    __syncthreads();
    __shared__ float s_mu, s_rstd;
    if (tid == 0) {
        float S = 0.f, Q = 0.f;
        #pragma unroll
        for (int i = 0; i < 8; i++) { S += rs_[i]; Q += rq_[i]; }
        float mu  = S * (1.f / DIM);
        float var = Q * (1.f / DIM) - mu * mu;
        s_mu = mu; s_rstd = rsqrtf(var + 1e-5f);
    }
    __syncthreads();
    const float mu = s_mu, rstd = s_rstd;
    const float4* gr = reinterpret_cast<const float4*>(gamma);
    const float4* br = reinterpret_cast<const float4*>(beta);
    uint2* dbf = reinterpret_cast<uint2*>(g_xbf + (size_t)t * DIM);
    uint2* dhi = reinterpret_cast<uint2*>(g_xhi + (size_t)t * DIM);
    uint2* dlo = reinterpret_cast<uint2*>(g_xlo + (size_t)t * DIM);
    #pragma unroll
    for (int j = 0; j < 2; j++) {
        const int i = tid + j * 256;
        float4 g = gr[i], b = br[i];
        float h0 = (v[j].x - mu) * rstd * g.x + b.x;
        float h1 = (v[j].y - mu) * rstd * g.y + b.y;
        float h2 = (v[j].z - mu) * rstd * g.z + b.z;
        float h3 = (v[j].w - mu) * rstd * g.w + b.w;
        __nv_bfloat162 pa = __floats2bfloat162_rn(h0, h1);
        __nv_bfloat162 pb = __floats2bfloat162_rn(h2, h3);
        uint2 u;
        u.x = *reinterpret_cast<unsigned int*>(&pa);
        u.y = *reinterpret_cast<unsigned int*>(&pb);
        dbf[i] = u;
        // fp16 hi/lo split of 1024*x (power-of-2 scale: exact)
        float f[4] = {v[j].x * 1024.f, v[j].y * 1024.f, v[j].z * 1024.f, v[j].w * 1024.f};
        __half hi[4], lo[4];
        #pragma unroll
        for (int c = 0; c < 4; c++) {
            hi[c] = __float2half_rn(f[c]);
            lo[c] = __float2half_rn(f[c] - __half2float(hi[c]));
        }
        __half2 h2a = __halves2half2(hi[0], hi[1]), h2b = __halves2half2(hi[2], hi[3]);
        __half2 l2a = __halves2half2(lo[0], lo[1]), l2b = __halves2half2(lo[2], lo[3]);
        uint2 uh, ul;
        uh.x = *reinterpret_cast<unsigned int*>(&h2a);
        uh.y = *reinterpret_cast<unsigned int*>(&h2b);
        ul.x = *reinterpret_cast<unsigned int*>(&l2a);
        ul.y = *reinterpret_cast<unsigned int*>(&l2b);
        dhi[i] = uh; dlo[i] = ul;
    }
    if (blockIdx.x == 0 && tid < 2 * NEXP) out[OFF_IMP + tid] = 0.f;
}

// ---------------------------------------------------------------------------
// Kernel 2a: W1 fp32 -> bf16.  Kernel 2b: Wg -> fp16 hi/lo (scaled 1024).
// ---------------------------------------------------------------------------
__global__ void __launch_bounds__(256) w1conv_kernel(const float* __restrict__ W1) {
    size_t i = (size_t)blockIdx.x * 256 + threadIdx.x;
    float4 v = reinterpret_cast<const float4*>(W1)[i];
    __nv_bfloat162 pa = __floats2bfloat162_rn(v.x, v.y);
    __nv_bfloat162 pb = __floats2bfloat162_rn(v.z, v.w);
    uint2 u;
    u.x = *reinterpret_cast<unsigned int*>(&pa);
    u.y = *reinterpret_cast<unsigned int*>(&pb);
    reinterpret_cast<uint2*>(g_w1bf)[i] = u;
}
__global__ void __launch_bounds__(256) wgsplit_kernel(const float* __restrict__ Wg) {
    size_t i = (size_t)blockIdx.x * 256 + threadIdx.x;
    float w = Wg[i] * 1024.f;
    __half hi = __float2half_rn(w);
    __half lo = __float2half_rn(w - __half2float(hi));
    g_wghi[i] = hi; g_wglo[i] = lo;
}

// ---------------------------------------------------------------------------
// Kernel 3: logits = x @ Wg^T via 3xfp16 split MMA (fp32-class precision).
// acc = hi.hi + hi.lo + lo.hi ; result * 2^-20. CTA 128x64, BK=64, 3-stage
// cp.async pipeline. 8 warps: warp_m = wid>>1 (32 rows), warp_n = wid&1.
// ---------------------------------------------------------------------------
__device__ __forceinline__ void copy_stageL(uint32_t st, const char* ahi, const char* alo,
                                            const char* bhi, const char* blo,
                                            int tid, size_t koff) {
    #pragma unroll
    for (int t = 0; t < 4; t++) {   // A: 128 rows x 8 units
        int u = tid + t * 256;
        int row = u >> 3, cu = u & 7;
        size_t g = (size_t)row * (DIM * 2) + koff + (size_t)cu * 16;
        uint32_t so = SWZ(row * 128 + cu * 16);
        CP_ASYNC16(st + so, ahi + g);
        CP_ASYNC16(st + 16384 + so, alo + g);
    }
    #pragma unroll
    for (int t = 0; t < 2; t++) {   // B: 64 rows x 8 units
        int u = tid + t * 256;
        int row = u >> 3, cu = u & 7;
        size_t g = (size_t)row * (DIM * 2) + koff + (size_t)cu * 16;
        uint32_t so = SWZ(row * 128 + cu * 16);
        CP_ASYNC16(st + 32768 + so, bhi + g);
        CP_ASYNC16(st + 40960 + so, blo + g);
    }
}

__global__ void __launch_bounds__(256, 1) logits_mma_kernel() {
    extern __shared__ char dynsmem[];
    const uint32_t raw  = smem_u32(dynsmem);
    const uint32_t base = (raw + 1023u) & ~1023u;

    const int tid = threadIdx.x, wid = tid >> 5, lane = tid & 31;
    const int warp_m = wid >> 1, warp_n = wid & 1;
    const int bm = blockIdx.x * 128;

    const char* ahi = reinterpret_cast<const char*>(g_xhi + (size_t)bm * DIM);
    const char* alo = reinterpret_cast<const char*>(g_xlo + (size_t)bm * DIM);
    const char* bhi = reinterpret_cast<const char*>(g_wghi);
    const char* blo = reinterpret_cast<const char*>(g_wglo);

    copy_stageL(base, ahi, alo, bhi, blo, tid, 0);       CP_COMMIT();
    copy_stageL(base + 49152, ahi, alo, bhi, blo, tid, 128); CP_COMMIT();

    float acc[2][4][4];
    #pragma unroll
    for (int a = 0; a < 2; a++)
        #pragma unroll
        for (int b = 0; b < 4; b++)
            #pragma unroll
            for (int c = 0; c < 4; c++) acc[a][b][c] = 0.f;

    #pragma unroll 1
    for (int i = 0; i < 32; i++) {
        if (i == 31) { CP_WAIT0(); } else { CP_WAIT1(); }
        __syncthreads();
        if (i + 2 < 32) {
            copy_stageL(base + ((i + 2) % 3) * 49152, ahi, alo, bhi, blo,
                        tid, (size_t)(i + 2) * 128);
            CP_COMMIT();
        }
        const uint32_t sA  = base + (i % 3) * 49152;
        const uint32_t sAl = sA + 16384;
        const uint32_t sB  = sA + 32768;
        const uint32_t sBl = sA + 40960;
        #pragma unroll
        for (int ks = 0; ks < 4; ks++) {
            uint32_t rah[2][4], ral[2][4];
            #pragma unroll
            for (int a = 0; a < 2; a++) {
                int row = warp_m * 32 + a * 16 + (lane & 15);
                int bc  = ks * 32 + (((lane >> 4) & 1) << 4);
                ldsm4(rah[a], sA + SWZ(row * 128 + bc));
                ldsm4(ral[a], sAl + SWZ(row * 128 + bc));
            }
            uint32_t rbh[4][2], rbl[4][2];
            #pragma unroll
            for (int bb = 0; bb < 4; bb += 2) {
                int nrow = warp_n * 32 + bb * 8 + (lane & 7) + ((lane >> 4) & 1) * 8;
                int kc   = ks * 32 + (((lane >> 3) & 1) << 4);
                uint32_t r[4];
                ldsm4(r, sB + SWZ(nrow * 128 + kc));
                rbh[bb][0] = r[0]; rbh[bb][1] = r[1];
                rbh[bb + 1][0] = r[2]; rbh[bb + 1][1] = r[3];
                ldsm4(r, sBl + SWZ(nrow * 128 + kc));
                rbl[bb][0] = r[0]; rbl[bb][1] = r[1];
                rbl[bb + 1][0] = r[2]; rbl[bb + 1][1] = r[3];
            }
            #pragma unroll
            for (int a = 0; a < 2; a++)
                #pragma unroll
                for (int b = 0; b < 4; b++) {
                    mma_f16(acc[a][b], rah[a], rbh[b]);
                    mma_f16(acc[a][b], rah[a], rbl[b]);
                    mma_f16(acc[a][b], ral[a], rbh[b]);
                }
        }
    }

    const float SC = 1.f / 1048576.f;   // 2^-20 (1024 * 1024 operand scaling)
    #pragma unroll
    for (int a = 0; a < 2; a++) {
        const int row = bm + warp_m * 32 + a * 16 + (lane >> 2);
        #pragma unroll
        for (int b = 0; b < 4; b++) {
            const int col = warp_n * 32 + b * 8 + 2 * (lane & 3);
            g_logits[(size_t)row * NEXP + col]           = acc[a][b][0] * SC;
            g_logits[(size_t)row * NEXP + col + 1]       = acc[a][b][1] * SC;
            g_logits[(size_t)(row + 8) * NEXP + col]     = acc[a][b][2] * SC;
            g_logits[(size_t)(row + 8) * NEXP + col + 1] = acc[a][b][3] * SC;
        }
    }
}

// ---------------------------------------------------------------------------
// Kernel 4: bf16 mma.sync GEMM h1 = LN(x)@W1^T, CTA 128x128, BK=64, 3-stage
// cp.async pipeline (single sync per chunk), fused GELU + W2-dot epilogue.
// 8 warps: warp_m = wid>>2 (64 rows), warp_n = wid&3 (32 cols).
// ---------------------------------------------------------------------------
__device__ __forceinline__ void copy_tiles(uint32_t sa, uint32_t sb,
                                           const char* ag, const char* bg, int tid) {
    #pragma unroll
    for (int t = 0; t < 4; t++) {
        int u = tid + t * 256;
        int row = u >> 3, cu = u & 7;
        size_t goff = (size_t)row * (DIM * 2) + (size_t)cu * 16;
        uint32_t soff = SWZ(row * 128 + cu * 16);
        CP_ASYNC16(sa + soff, ag + goff);
        CP_ASYNC16(sb + soff, bg + goff);
    }
}

__device__ __forceinline__ void compute_chunk(uint32_t abase, uint32_t bbase,
                                              int warp_m, int warp_n, int lane,
                                              float acc[4][4][4]) {
    #pragma unroll
    for (int ks = 0; ks < 4; ks++) {
        uint32_t ra[4][4];
        #pragma unroll
        for (int a = 0; a < 4; a++) {
            int row = warp_m * 64 + a * 16 + (lane & 15);
            int bc  = ks * 32 + (((lane >> 4) & 1) << 4);
            ldsm4(ra[a], abase + SWZ(row * 128 + bc));
        }
        uint32_t rb[4][2];
        #pragma unroll
        for (int bb = 0; bb < 4; bb += 2) {
            int nrow = warp_n * 32 + bb * 8 + (lane & 7) + ((lane >> 4) & 1) * 8;
            int kc   = ks * 32 + (((lane >> 3) & 1) << 4);
            uint32_t r[4];
            ldsm4(r, bbase + SWZ(nrow * 128 + kc));
            rb[bb][0] = r[0];     rb[bb][1] = r[1];
            rb[bb + 1][0] = r[2]; rb[bb + 1][1] = r[3];
        }
        #pragma unroll
        for (int a = 0; a < 4; a++)
            #pragma unroll
            for (int b = 0; b < 4; b++)
                mma_bf16(acc[a][b], ra[a], rb[b]);
    }
}

__global__ void __launch_bounds__(256, 1) h1z_kernel(const float* __restrict__ W2) {
    extern __shared__ char dynsmem[];
    const uint32_t raw  = smem_u32(dynsmem);
    const uint32_t base = (raw + 1023u) & ~1023u;
    char* sm = dynsmem + (base - raw);
    const int OW2 = 98304, OZ = 98816;   // after 3 x 32KB stages

    const int tid = threadIdx.x, wid = tid >> 5, lane = tid & 31;
    const int warp_m = wid >> 2, warp_n = wid & 3;
    const int bn = blockIdx.x * 128;
    const int bm = blockIdx.y * 128;

    float* w2s  = reinterpret_cast<float*>(sm + OW2);
    float* zrow = reinterpret_cast<float*>(sm + OZ);
    if (tid < 128) { w2s[tid] = W2[bn + tid]; zrow[tid] = 0.f; }

    const char* ag = reinterpret_cast<const char*>(g_xbf + (size_t)bm * DIM);
    const char* bg = reinterpret_cast<const char*>(g_w1bf + (size_t)bn * DIM);

    copy_tiles(base, base + 16384, ag, bg, tid);                         CP_COMMIT();
    copy_tiles(base + 32768, base + 49152, ag + 128, bg + 128, tid);     CP_COMMIT();

    float acc[4][4][4];
    #pragma unroll
    for (int a = 0; a < 4; a++)
        #pragma unroll
        for (int b = 0; b < 4; b++)
            #pragma unroll
            for (int c = 0; c < 4; c++) acc[a][b][c] = 0.f;

    #pragma unroll 1
    for (int i = 0; i < 32; i++) {
        if (i == 31) { CP_WAIT0(); } else { CP_WAIT1(); }
        __syncthreads();
        if (i + 2 < 32) {
            const uint32_t st = base + ((i + 2) % 3) * 32768;
            copy_tiles(st, st + 16384, ag + (size_t)(i + 2) * 128,
                       bg + (size_t)(i + 2) * 128, tid);
            CP_COMMIT();
        }
        const uint32_t cs = base + (i % 3) * 32768;
        compute_chunk(cs, cs + 16384, warp_m, warp_n, lane, acc);
    }

    // Fused epilogue: GELU + dot with W2, row-reduce.
    float z[8];
    #pragma unroll
    for (int j = 0; j < 8; j++) z[j] = 0.f;
    #pragma unroll
    for (int a = 0; a < 4; a++) {
        #pragma unroll
        for (int b = 0; b < 4; b++) {
            const int colb = warp_n * 32 + b * 8 + 2 * (lane & 3);
            const float w0 = w2s[colb], w1 = w2s[colb + 1];
            float v0 = acc[a][b][0], v1 = acc[a][b][1];
            float v2 = acc[a][b][2], v3 = acc[a][b][3];
            v0 = 0.5f * v0 * (1.f + erff(v0 * 0.70710678118654752f));
            v1 = 0.5f * v1 * (1.f + erff(v1 * 0.70710678118654752f));
            v2 = 0.5f * v2 * (1.f + erff(v2 * 0.70710678118654752f));
            v3 = 0.5f * v3 * (1.f + erff(v3 * 0.70710678118654752f));
            z[a * 2 + 0] += v0 * w0 + v1 * w1;
            z[a * 2 + 1] += v2 * w0 + v3 * w1;
        }
    }
    #pragma unroll
    for (int m = 1; m <= 2; m <<= 1)
        #pragma unroll
        for (int j = 0; j < 8; j++)
            z[j] += __shfl_xor_sync(0xffffffffu, z[j], m);
    if ((lane & 3) == 0) {
        #pragma unroll
        for (int a = 0; a < 4; a++) {
            const int r0 = warp_m * 64 + a * 16 + (lane >> 2);
            atomicAdd(&zrow[r0], z[a * 2 + 0]);
            atomicAdd(&zrow[r0 + 8], z[a * 2 + 1]);
        }
    }
    __syncthreads();
    if (tid < 128) g_zpart[blockIdx.x][bm + tid] = zrow[tid];
}

// ---------------------------------------------------------------------------
// Kernel 5: warp-per-token epilogue (unchanged, verified R8).
// ---------------------------------------------------------------------------
__global__ void __launch_bounds__(256) epilogue_kernel(float* __restrict__ out) {
    __shared__ float s_imp[NEXP], s_load[NEXP];
    const int tid = threadIdx.x;
    if (tid < NEXP) s_imp[tid] = 0.f;
    else if (tid < 2 * NEXP) s_load[tid - NEXP] = 0.f;
    __syncthreads();

    const int w = tid >> 5, lane = tid & 31;
    const int t = blockIdx.x * 8 + w;

    float zp = (lane < NXT) ? g_zpart[lane][t] : 0.f;
    #pragma unroll
    for (int o = 16; o; o >>= 1) zp += __shfl_xor_sync(0xffffffffu, zp, o);
    const float sc = 1.f / (1.f + 1.f / (1.f + expf(-zp)));

    const float* lrow = g_logits + (size_t)t * NEXP;
    const float l0 = lrow[lane] * sc;
    const float l1 = lrow[lane + 32] * sc;

    float m = fmaxf(l0, l1);
    #pragma unroll
    for (int o = 16; o; o >>= 1) m = fmaxf(m, __shfl_xor_sync(0xffffffffu, m, o));
    const float e0 = expf(l0 - m), e1 = expf(l1 - m);
    float se = e0 + e1;
    #pragma unroll
    for (int o = 16; o; o >>= 1) se += __shfl_xor_sync(0xffffffffu, se, o);
    const float inv = 1.f / se;
    const float p0 = e0 * inv, p1 = e1 * inv;

    out[OFF_PROBS + (size_t)t * NEXP + lane]      = p0;
    out[OFF_PROBS + (size_t)t * NEXP + lane + 32] = p1;
    atomicAdd(&s_imp[lane], p0);
    atomicAdd(&s_imp[lane + 32], p1);

    float v; int ei;
    if (l1 > l0) { v = l1; ei = lane + 32; } else { v = l0; ei = lane; }
    #pragma unroll
    for (int o = 16; o; o >>= 1) {
        float ov = __shfl_xor_sync(0xffffffffu, v, o);
        int   oi = __shfl_xor_sync(0xffffffffu, ei, o);
        if (ov > v || (ov == v && oi < ei)) { v = ov; ei = oi; }
    }
    const int i0 = ei;
    float a0 = (lane == i0)      ? -3.4e38f : l0;
    float a1 = (lane + 32 == i0) ? -3.4e38f : l1;
    if (a1 > a0) { v = a1; ei = lane + 32; } else { v = a0; ei = lane; }
    #pragma unroll
    for (int o = 16; o; o >>= 1) {
        float ov = __shfl_xor_sync(0xffffffffu, v, o);
        int   oi = __shfl_xor_sync(0xffffffffu, ei, o);
        if (ov > v || (ov == v && oi < ei)) { v = ov; ei = oi; }
    }
    const int i1 = ei;

    const float c0 = (i0 < 32) ? p0 : p1;
    const float pi0 = __shfl_sync(0xffffffffu, c0, i0 & 31);
    const float c1 = (i1 < 32) ? p0 : p1;
    const float pi1 = __shfl_sync(0xffffffffu, c1, i1 & 31);

    if (lane == 0) {
        const float s0 = (1.0f - pi0) + pi0;
        const float s1 = (1.0f - pi1) + pi1;
        const float sn = fmaxf(s0 + s1, 1e-9f);
        out[OFF_IDX + t * 2 + 0]    = (float)i0;
        out[OFF_IDX + t * 2 + 1]    = (float)i1;
        out[OFF_SCORES + t * 2 + 0] = s0 / sn;
        out[OFF_SCORES + t * 2 + 1] = s1 / sn;
        atomicAdd(&s_load[i0], 1.f);
        atomicAdd(&s_load[i1], 1.f);
    }
    __syncthreads();
    if (tid < NEXP)
        atomicAdd(&out[OFF_IMP + tid], s_imp[tid] * (1.f / BS_TOK));
    else if (tid < 2 * NEXP)
        atomicAdd(&out[OFF_LOAD + tid - NEXP], s_load[tid - NEXP] * (1.f / BS_TOK));
}

// ---------------------------------------------------------------------------
// kernel_launch: graph-capturable sequence.
// Inputs: x[B,S,D], Wg[E,D], gamma[D], beta[D], W1[H,D], W2[1,H] (fp32)
// ---------------------------------------------------------------------------
extern "C" void kernel_launch(void* const* d_in, const int* in_sizes, int n_in,
                              void* d_out, int out_size) {
    const float* x     = (const float*)d_in[0];
    const float* Wg    = (const float*)d_in[1];
    const float* gamma = (const float*)d_in[2];
    const float* beta  = (const float*)d_in[3];
    const float* W1    = (const float*)d_in[4];
    const float* W2    = (const float*)d_in[5];
    float* out = (float*)d_out;

    cudaFuncSetAttribute(h1z_kernel, cudaFuncAttributeMaxDynamicSharedMemorySize, 100352);
    cudaFuncSetAttribute(logits_mma_kernel, cudaFuncAttributeMaxDynamicSharedMemorySize, 148480);

    // 1) LN + bf16 convert + fp16 x split + zero accumulators
    prep_kernel<<<BS_TOK, 256>>>(x, gamma, beta, out);
    // 2) weight conversions
    w1conv_kernel<<<(HID * DIM / 4) / 256, 256>>>(W1);
    wgsplit_kernel<<<(NEXP * DIM) / 256, 256>>>(Wg);
    // 3) logits via 3xfp16 split MMA (fp32-class precision, tensor pipe)
    logits_mma_kernel<<<BS_TOK / 128, 256, 148480>>>();
    // 4) bf16 mma.sync h1 GEMM + fused GELU/W2-dot (3-stage pipeline)
    h1z_kernel<<<dim3(NXT, BS_TOK / 128), 256, 100352>>>(W2);
    // 5) softmax / top-2 / outputs
    epilogue_kernel<<<BS_TOK / 8, 256>>>(out);

    (void)in_sizes; (void)n_in; (void)out_size;
}

// round 13
// speedup vs baseline: 9.1883x; 1.0117x over previous
#include <cuda_runtime.h>
#include <cuda_fp16.h>
#include <math.h>
#include <stdint.h>

// Problem constants (fixed by setup_inputs)
#define BS_TOK 16384   // B*S
#define DIM    2048    // D
#define NEXP   64      // E
#define HID    1024    // D/2
#define NXT    (HID / 128)   // 8 N-tiles in the h1 GEMM

// Output layout (flattened tuple, fp32):
// idx[BS,2] | scores[BS,2] | probs_soft[BS,64] | importance[64] | load[64]
#define OFF_IDX    0
#define OFF_SCORES (BS_TOK * 2)
#define OFF_PROBS  (BS_TOK * 4)
#define OFF_IMP    (BS_TOK * 4 + BS_TOK * NEXP)
#define OFF_LOAD   (OFF_IMP + NEXP)

// Scratch (device globals: allocation-free)
__device__ __half g_xhi[(size_t)BS_TOK * DIM];          // fp16 hi of 1024*x
__device__ __half g_xlo[(size_t)BS_TOK * DIM];          // fp16 lo of 1024*x
__device__ __half g_w1h[(size_t)HID * DIM];             // fp16 of W1*gamma
__device__ __half g_wghi[(size_t)NEXP * DIM];           // fp16 hi of 1024*Wg
__device__ __half g_wglo[(size_t)NEXP * DIM];           // fp16 lo of 1024*Wg
__device__ float g_c1[HID];                             // sum_d gamma_d*W1[h,d]
__device__ float g_c2[HID];                             // sum_d beta_d*W1[h,d]
__device__ float g_mu[BS_TOK];
__device__ float g_rstd[BS_TOK];
__device__ float g_logits[(size_t)BS_TOK * NEXP];
__device__ float g_zpart[NXT][BS_TOK];

// ---------------------------------------------------------------------------
// PTX helpers — family-portable only (no tcgen05: ptxas targets sm_103 base)
// ---------------------------------------------------------------------------
__device__ __forceinline__ uint32_t smem_u32(const void* p) {
    uint32_t a;
    asm("{ .reg .u64 t; cvta.to.shared.u64 t, %1; cvt.u32.u64 %0, t; }" : "=r"(a) : "l"(p));
    return a;
}
#define SWZ(o) ((o) ^ (((o) >> 3) & 0x70))
#define CP_ASYNC16(dst, src) \
    asm volatile("cp.async.cg.shared.global [%0], [%1], 16;" :: "r"(dst), "l"(src))
#define CP_COMMIT() asm volatile("cp.async.commit_group;" ::: "memory")
#define CP_WAIT1()  asm volatile("cp.async.wait_group 1;" ::: "memory")
#define CP_WAIT0()  asm volatile("cp.async.wait_group 0;" ::: "memory")

__device__ __forceinline__ void ldsm4(uint32_t* r, uint32_t addr) {
    asm volatile("ldmatrix.sync.aligned.m8n8.x4.shared.b16 {%0,%1,%2,%3}, [%4];"
                 : "=r"(r[0]), "=r"(r[1]), "=r"(r[2]), "=r"(r[3]) : "r"(addr));
}
__device__ __forceinline__ void mma_f16(float* c, const uint32_t* a, const uint32_t* b) {
    asm volatile(
        "mma.sync.aligned.m16n8k16.row.col.f32.f16.f16.f32 "
        "{%0,%1,%2,%3}, {%4,%5,%6,%7}, {%8,%9}, {%0,%1,%2,%3};"
        : "+f"(c[0]), "+f"(c[1]), "+f"(c[2]), "+f"(c[3])
        : "r"(a[0]), "r"(a[1]), "r"(a[2]), "r"(a[3]), "r"(b[0]), "r"(b[1]));
}

// ---------------------------------------------------------------------------
// Kernel 1: per-token stats (mu, rstd) + fp16 hi/lo split of 1024*x.
// Zeroes importance/load accumulators (required every graph replay).
// ---------------------------------------------------------------------------
__global__ void __launch_bounds__(256) prep_kernel(
    const float* __restrict__ x, float* __restrict__ out) {
    const int t = blockIdx.x, tid = threadIdx.x;
    const float4* xr = reinterpret_cast<const float4*>(x + (size_t)t * DIM);

    float4 v[2];
    v[0] = xr[tid];
    v[1] = xr[tid + 256];

    float s = 0.f, sq = 0.f;
    #pragma unroll
    for (int j = 0; j < 2; j++) {
        s  += v[j].x + v[j].y + v[j].z + v[j].w;
        sq += v[j].x * v[j].x + v[j].y * v[j].y + v[j].z * v[j].z + v[j].w * v[j].w;
    }
    __shared__ float rs_[8], rq_[8];
    #pragma unroll
    for (int o = 16; o; o >>= 1) {
        s  += __shfl_down_sync(0xffffffffu, s, o);
        sq += __shfl_down_sync(0xffffffffu, sq, o);
    }
    if ((tid & 31) == 0) { rs_[tid >> 5] = s; rq_[tid >> 5] = sq; }
    __syncthreads();
    if (tid == 0) {
        float S = 0.f, Q = 0.f;
        #pragma unroll
        for (int i = 0; i < 8; i++) { S += rs_[i]; Q += rq_[i]; }
        float mu  = S * (1.f / DIM);
        float var = Q * (1.f / DIM) - mu * mu;
        g_mu[t]   = mu;
        g_rstd[t] = rsqrtf(var + 1e-5f);
    }
    uint2* dhi = reinterpret_cast<uint2*>(g_xhi + (size_t)t * DIM);
    uint2* dlo = reinterpret_cast<uint2*>(g_xlo + (size_t)t * DIM);
    #pragma unroll
    for (int j = 0; j < 2; j++) {
        const int i = tid + j * 256;
        float f[4] = {v[j].x * 1024.f, v[j].y * 1024.f, v[j].z * 1024.f, v[j].w * 1024.f};
        __half hi[4], lo[4];
        #pragma unroll
        for (int c = 0; c < 4; c++) {
            hi[c] = __float2half_rn(f[c]);
            lo[c] = __float2half_rn(f[c] - __half2float(hi[c]));
        }
        __half2 h2a = __halves2half2(hi[0], hi[1]), h2b = __halves2half2(hi[2], hi[3]);
        __half2 l2a = __halves2half2(lo[0], lo[1]), l2b = __halves2half2(lo[2], lo[3]);
        uint2 uh, ul;
        uh.x = *reinterpret_cast<unsigned int*>(&h2a);
        uh.y = *reinterpret_cast<unsigned int*>(&h2b);
        ul.x = *reinterpret_cast<unsigned int*>(&l2a);
        ul.y = *reinterpret_cast<unsigned int*>(&l2b);
        dhi[i] = uh; dlo[i] = ul;
    }
    if (blockIdx.x == 0 && tid < 2 * NEXP) out[OFF_IMP + tid] = 0.f;
}

// ---------------------------------------------------------------------------
// Kernel 2a: W1*gamma -> fp16.  2b: Wg -> fp16 hi/lo (scaled 1024).
// 2c: c1[h] = sum_d gamma_d W1[h,d], c2[h] = sum_d beta_d W1[h,d].
// ---------------------------------------------------------------------------
__global__ void __launch_bounds__(256) w1conv_kernel(
    const float* __restrict__ W1, const float* __restrict__ gamma) {
    size_t i = (size_t)blockIdx.x * 256 + threadIdx.x;
    float4 v = reinterpret_cast<const float4*>(W1)[i];
    float4 g = reinterpret_cast<const float4*>(gamma)[i % (DIM / 4)];
    __half2 pa = __floats2half2_rn(v.x * g.x, v.y * g.y);
    __half2 pb = __floats2half2_rn(v.z * g.z, v.w * g.w);
    uint2 u;
    u.x = *reinterpret_cast<unsigned int*>(&pa);
    u.y = *reinterpret_cast<unsigned int*>(&pb);
    reinterpret_cast<uint2*>(g_w1h)[i] = u;
}
__global__ void __launch_bounds__(256) wgsplit_kernel(const float* __restrict__ Wg) {
    size_t i = (size_t)blockIdx.x * 256 + threadIdx.x;
    float w = Wg[i] * 1024.f;
    __half hi = __float2half_rn(w);
    __half lo = __float2half_rn(w - __half2float(hi));
    g_wghi[i] = hi; g_wglo[i] = lo;
}
__global__ void __launch_bounds__(256) cvec_kernel(
    const float* __restrict__ W1, const float* __restrict__ gamma,
    const float* __restrict__ beta) {
    const int h = blockIdx.x, tid = threadIdx.x;
    const float4* wr = reinterpret_cast<const float4*>(W1 + (size_t)h * DIM);
    const float4* gr = reinterpret_cast<const float4*>(gamma);
    const float4* br = reinterpret_cast<const float4*>(beta);
    float c1 = 0.f, c2 = 0.f;
    #pragma unroll 2
    for (int i = tid; i < DIM / 4; i += 256) {
        float4 w = wr[i], g = gr[i], b = br[i];
        c1 += w.x * g.x + w.y * g.y + w.z * g.z + w.w * g.w;
        c2 += w.x * b.x + w.y * b.y + w.z * b.z + w.w * b.w;
    }
    __shared__ float r1[8], r2[8];
    #pragma unroll
    for (int o = 16; o; o >>= 1) {
        c1 += __shfl_down_sync(0xffffffffu, c1, o);
        c2 += __shfl_down_sync(0xffffffffu, c2, o);
    }
    if ((tid & 31) == 0) { r1[tid >> 5] = c1; r2[tid >> 5] = c2; }
    __syncthreads();
    if (tid == 0) {
        float a = 0.f, b = 0.f;
        #pragma unroll
        for (int i = 0; i < 8; i++) { a += r1[i]; b += r2[i]; }
        g_c1[h] = a; g_c2[h] = b;
    }
}

// ---------------------------------------------------------------------------
// Kernel 3: logits = x @ Wg^T via 3xfp16 split MMA (unchanged, verified R9).
// ---------------------------------------------------------------------------
__device__ __forceinline__ void copy_stageL(uint32_t st, const char* ahi, const char* alo,
                                            const char* bhi, const char* blo,
                                            int tid, size_t koff) {
    #pragma unroll
    for (int t = 0; t < 4; t++) {   // A: 128 rows x 8 units
        int u = tid + t * 256;
        int row = u >> 3, cu = u & 7;
        size_t g = (size_t)row * (DIM * 2) + koff + (size_t)cu * 16;
        uint32_t so = SWZ(row * 128 + cu * 16);
        CP_ASYNC16(st + so, ahi + g);
        CP_ASYNC16(st + 16384 + so, alo + g);
    }
    #pragma unroll
    for (int t = 0; t < 2; t++) {   // B: 64 rows x 8 units
        int u = tid + t * 256;
        int row = u >> 3, cu = u & 7;
        size_t g = (size_t)row * (DIM * 2) + koff + (size_t)cu * 16;
        uint32_t so = SWZ(row * 128 + cu * 16);
        CP_ASYNC16(st + 32768 + so, bhi + g);
        CP_ASYNC16(st + 40960 + so, blo + g);
    }
}

__global__ void __launch_bounds__(256, 1) logits_mma_kernel() {
    extern __shared__ char dynsmem[];
    const uint32_t raw  = smem_u32(dynsmem);
    const uint32_t base = (raw + 1023u) & ~1023u;

    const int tid = threadIdx.x, wid = tid >> 5, lane = tid & 31;
    const int warp_m = wid >> 1, warp_n = wid & 1;
    const int bm = blockIdx.x * 128;

    const char* ahi = reinterpret_cast<const char*>(g_xhi + (size_t)bm * DIM);
    const char* alo = reinterpret_cast<const char*>(g_xlo + (size_t)bm * DIM);
    const char* bhi = reinterpret_cast<const char*>(g_wghi);
    const char* blo = reinterpret_cast<const char*>(g_wglo);

    copy_stageL(base, ahi, alo, bhi, blo, tid, 0);           CP_COMMIT();
    copy_stageL(base + 49152, ahi, alo, bhi, blo, tid, 128); CP_COMMIT();

    float acc[2][4][4];
    #pragma unroll
    for (int a = 0; a < 2; a++)
        #pragma unroll
        for (int b = 0; b < 4; b++)
            #pragma unroll
            for (int c = 0; c < 4; c++) acc[a][b][c] = 0.f;

    #pragma unroll 1
    for (int i = 0; i < 32; i++) {
        if (i == 31) { CP_WAIT0(); } else { CP_WAIT1(); }
        __syncthreads();
        if (i + 2 < 32) {
            copy_stageL(base + ((i + 2) % 3) * 49152, ahi, alo, bhi, blo,
                        tid, (size_t)(i + 2) * 128);
            CP_COMMIT();
        }
        const uint32_t sA  = base + (i % 3) * 49152;
        const uint32_t sAl = sA + 16384;
        const uint32_t sB  = sA + 32768;
        const uint32_t sBl = sA + 40960;
        #pragma unroll
        for (int ks = 0; ks < 4; ks++) {
            uint32_t rah[2][4], ral[2][4];
            #pragma unroll
            for (int a = 0; a < 2; a++) {
                int row = warp_m * 32 + a * 16 + (lane & 15);
                int bc  = ks * 32 + (((lane >> 4) & 1) << 4);
                ldsm4(rah[a], sA + SWZ(row * 128 + bc));
                ldsm4(ral[a], sAl + SWZ(row * 128 + bc));
            }
            uint32_t rbh[4][2], rbl[4][2];
            #pragma unroll
            for (int bb = 0; bb < 4; bb += 2) {
                int nrow = warp_n * 32 + bb * 8 + (lane & 7) + ((lane >> 4) & 1) * 8;
                int kc   = ks * 32 + (((lane >> 3) & 1) << 4);
                uint32_t r[4];
                ldsm4(r, sB + SWZ(nrow * 128 + kc));
                rbh[bb][0] = r[0]; rbh[bb][1] = r[1];
                rbh[bb + 1][0] = r[2]; rbh[bb + 1][1] = r[3];
                ldsm4(r, sBl + SWZ(nrow * 128 + kc));
                rbl[bb][0] = r[0]; rbl[bb][1] = r[1];
                rbl[bb + 1][0] = r[2]; rbl[bb + 1][1] = r[3];
            }
            #pragma unroll
            for (int a = 0; a < 2; a++)
                #pragma unroll
                for (int b = 0; b < 4; b++) {
                    mma_f16(acc[a][b], rah[a], rbh[b]);
                    mma_f16(acc[a][b], rah[a], rbl[b]);
                    mma_f16(acc[a][b], ral[a], rbh[b]);
                }
        }
    }

    const float SC = 1.f / 1048576.f;   // 2^-20 (1024 * 1024 operand scaling)
    #pragma unroll
    for (int a = 0; a < 2; a++) {
        const int row = bm + warp_m * 32 + a * 16 + (lane >> 2);
        #pragma unroll
        for (int b = 0; b < 4; b++) {
            const int col = warp_n * 32 + b * 8 + 2 * (lane & 3);
            g_logits[(size_t)row * NEXP + col]           = acc[a][b][0] * SC;
            g_logits[(size_t)row * NEXP + col + 1]       = acc[a][b][1] * SC;
            g_logits[(size_t)(row + 8) * NEXP + col]     = acc[a][b][2] * SC;
            g_logits[(size_t)(row + 8) * NEXP + col + 1] = acc[a][b][3] * SC;
        }
    }
}

// ---------------------------------------------------------------------------
// Kernel 4: fp16 mma GEMM acc = (1024*x) @ (W1*gamma)^T, CTA 128x128, BK=64,
// 3-stage cp.async pipeline. Epilogue applies the exact LN affine:
//   h1 = rstd*(acc/1024) - rstd*mu*c1[col] + c2[col], then GELU, then W2-dot.
// ---------------------------------------------------------------------------
__device__ __forceinline__ void copy_tiles(uint32_t sa, uint32_t sb,
                                           const char* ag, const char* bg, int tid) {
    #pragma unroll
    for (int t = 0; t < 4; t++) {
        int u = tid + t * 256;
        int row = u >> 3, cu = u & 7;
        size_t goff = (size_t)row * (DIM * 2) + (size_t)cu * 16;
        uint32_t soff = SWZ(row * 128 + cu * 16);
        CP_ASYNC16(sa + soff, ag + goff);
        CP_ASYNC16(sb + soff, bg + goff);
    }
}

__device__ __forceinline__ void compute_chunk(uint32_t abase, uint32_t bbase,
                                              int warp_m, int warp_n, int lane,
                                              float acc[4][4][4]) {
    #pragma unroll
    for (int ks = 0; ks < 4; ks++) {
        uint32_t ra[4][4];
        #pragma unroll
        for (int a = 0; a < 4; a++) {
            int row = warp_m * 64 + a * 16 + (lane & 15);
            int bc  = ks * 32 + (((lane >> 4) & 1) << 4);
            ldsm4(ra[a], abase + SWZ(row * 128 + bc));
        }
        uint32_t rb[4][2];
        #pragma unroll
        for (int bb = 0; bb < 4; bb += 2) {
            int nrow = warp_n * 32 + bb * 8 + (lane & 7) + ((lane >> 4) & 1) * 8;
            int kc   = ks * 32 + (((lane >> 3) & 1) << 4);
            uint32_t r[4];
            ldsm4(r, bbase + SWZ(nrow * 128 + kc));
            rb[bb][0] = r[0];     rb[bb][1] = r[1];
            rb[bb + 1][0] = r[2]; rb[bb + 1][1] = r[3];
        }
        #pragma unroll
        for (int a = 0; a < 4; a++)
            #pragma unroll
            for (int b = 0; b < 4; b++)
                mma_f16(acc[a][b], ra[a], rb[b]);
    }
}

__global__ void __launch_bounds__(256, 1) h1z_kernel(const float* __restrict__ W2) {
    extern __shared__ char dynsmem[];
    const uint32_t raw  = smem_u32(dynsmem);
    const uint32_t base = (raw + 1023u) & ~1023u;
    char* sm = dynsmem + (base - raw);
    const int OW2 = 98304, OZ = 98816, OC1 = 99328, OC2 = 99840;
    const int OMU = 100352, ORS = 100864;

    const int tid = threadIdx.x, wid = tid >> 5, lane = tid & 31;
    const int warp_m = wid >> 2, warp_n = wid & 3;
    const int bn = blockIdx.x * 128;
    const int bm = blockIdx.y * 128;

    float* w2s  = reinterpret_cast<float*>(sm + OW2);
    float* zrow = reinterpret_cast<float*>(sm + OZ);
    float* sc1  = reinterpret_cast<float*>(sm + OC1);
    float* sc2  = reinterpret_cast<float*>(sm + OC2);
    float* smu  = reinterpret_cast<float*>(sm + OMU);
    float* srs  = reinterpret_cast<float*>(sm + ORS);
    if (tid < 128) {
        w2s[tid] = W2[bn + tid];
        zrow[tid] = 0.f;
        sc1[tid] = g_c1[bn + tid];
        sc2[tid] = g_c2[bn + tid];
        smu[tid] = g_mu[bm + tid];
        srs[tid] = g_rstd[bm + tid];
    }

    const char* ag = reinterpret_cast<const char*>(g_xhi + (size_t)bm * DIM);
    const char* bg = reinterpret_cast<const char*>(g_w1h + (size_t)bn * DIM);

    copy_tiles(base, base + 16384, ag, bg, tid);                      CP_COMMIT();
    copy_tiles(base + 32768, base + 49152, ag + 128, bg + 128, tid);  CP_COMMIT();

    float acc[4][4][4];
    #pragma unroll
    for (int a = 0; a < 4; a++)
        #pragma unroll
        for (int b = 0; b < 4; b++)
            #pragma unroll
            for (int c = 0; c < 4; c++) acc[a][b][c] = 0.f;

    #pragma unroll 1
    for (int i = 0; i < 32; i++) {
        if (i == 31) { CP_WAIT0(); } else { CP_WAIT1(); }
        __syncthreads();
        if (i + 2 < 32) {
            const uint32_t st = base + ((i + 2) % 3) * 32768;
            copy_tiles(st, st + 16384, ag + (size_t)(i + 2) * 128,
                       bg + (size_t)(i + 2) * 128, tid);
            CP_COMMIT();
        }
        const uint32_t cs = base + (i % 3) * 32768;
        compute_chunk(cs, cs + 16384, warp_m, warp_n, lane, acc);
    }

    // Fused epilogue: exact LN affine + GELU + dot with W2, row-reduce.
    float z[8];
    #pragma unroll
    for (int j = 0; j < 8; j++) z[j] = 0.f;
    #pragma unroll
    for (int a = 0; a < 4; a++) {
        const int r0 = warp_m * 64 + a * 16 + (lane >> 2);
        const float rs0 = srs[r0], mu0 = smu[r0];
        const float rs1 = srs[r0 + 8], mu1 = smu[r0 + 8];
        #pragma unroll
        for (int b = 0; b < 4; b++) {
            const int colb = warp_n * 32 + b * 8 + 2 * (lane & 3);
            const float w0 = w2s[colb], w1 = w2s[colb + 1];
            const float c10 = sc1[colb], c11 = sc1[colb + 1];
            const float c20 = sc2[colb], c21 = sc2[colb + 1];
            float v0 = rs0 * (acc[a][b][0] * (1.f / 1024.f) - mu0 * c10) + c20;
            float v1 = rs0 * (acc[a][b][1] * (1.f / 1024.f) - mu0 * c11) + c21;
            float v2 = rs1 * (acc[a][b][2] * (1.f / 1024.f) - mu1 * c10) + c20;
            float v3 = rs1 * (acc[a][b][3] * (1.f / 1024.f) - mu1 * c11) + c21;
            v0 = 0.5f * v0 * (1.f + erff(v0 * 0.70710678118654752f));
            v1 = 0.5f * v1 * (1.f + erff(v1 * 0.70710678118654752f));
            v2 = 0.5f * v2 * (1.f + erff(v2 * 0.70710678118654752f));
            v3 = 0.5f * v3 * (1.f + erff(v3 * 0.70710678118654752f));
            z[a * 2 + 0] += v0 * w0 + v1 * w1;
            z[a * 2 + 1] += v2 * w0 + v3 * w1;
        }
    }
    #pragma unroll
    for (int m = 1; m <= 2; m <<= 1)
        #pragma unroll
        for (int j = 0; j < 8; j++)
            z[j] += __shfl_xor_sync(0xffffffffu, z[j], m);
    if ((lane & 3) == 0) {
        #pragma unroll
        for (int a = 0; a < 4; a++) {
            const int r0 = warp_m * 64 + a * 16 + (lane >> 2);
            atomicAdd(&zrow[r0], z[a * 2 + 0]);
            atomicAdd(&zrow[r0 + 8], z[a * 2 + 1]);
        }
    }
    __syncthreads();
    if (tid < 128) g_zpart[blockIdx.x][bm + tid] = zrow[tid];
}

// ---------------------------------------------------------------------------
// Kernel 5: warp-per-token epilogue (unchanged, verified R8/R9).
// ---------------------------------------------------------------------------
__global__ void __launch_bounds__(256) epilogue_kernel(float* __restrict__ out) {
    __shared__ float s_imp[NEXP], s_load[NEXP];
    const int tid = threadIdx.x;
    if (tid < NEXP) s_imp[tid] = 0.f;
    else if (tid < 2 * NEXP) s_load[tid - NEXP] = 0.f;
    __syncthreads();

    const int w = tid >> 5, lane = tid & 31;
    const int t = blockIdx.x * 8 + w;

    float zp = (lane < NXT) ? g_zpart[lane][t] : 0.f;
    #pragma unroll
    for (int o = 16; o; o >>= 1) zp += __shfl_xor_sync(0xffffffffu, zp, o);
    const float sc = 1.f / (1.f + 1.f / (1.f + expf(-zp)));

    const float* lrow = g_logits + (size_t)t * NEXP;
    const float l0 = lrow[lane] * sc;
    const float l1 = lrow[lane + 32] * sc;

    float m = fmaxf(l0, l1);
    #pragma unroll
    for (int o = 16; o; o >>= 1) m = fmaxf(m, __shfl_xor_sync(0xffffffffu, m, o));
    const float e0 = expf(l0 - m), e1 = expf(l1 - m);
    float se = e0 + e1;
    #pragma unroll
    for (int o = 16; o; o >>= 1) se += __shfl_xor_sync(0xffffffffu, se, o);
    const float inv = 1.f / se;
    const float p0 = e0 * inv, p1 = e1 * inv;

    out[OFF_PROBS + (size_t)t * NEXP + lane]      = p0;
    out[OFF_PROBS + (size_t)t * NEXP + lane + 32] = p1;
    atomicAdd(&s_imp[lane], p0);
    atomicAdd(&s_imp[lane + 32], p1);

    float v; int ei;
    if (l1 > l0) { v = l1; ei = lane + 32; } else { v = l0; ei = lane; }
    #pragma unroll
    for (int o = 16; o; o >>= 1) {
        float ov = __shfl_xor_sync(0xffffffffu, v, o);
        int   oi = __shfl_xor_sync(0xffffffffu, ei, o);
        if (ov > v || (ov == v && oi < ei)) { v = ov; ei = oi; }
    }
    const int i0 = ei;
    float a0 = (lane == i0)      ? -3.4e38f : l0;
    float a1 = (lane + 32 == i0) ? -3.4e38f : l1;
    if (a1 > a0) { v = a1; ei = lane + 32; } else { v = a0; ei = lane; }
    #pragma unroll
    for (int o = 16; o; o >>= 1) {
        float ov = __shfl_xor_sync(0xffffffffu, v, o);
        int   oi = __shfl_xor_sync(0xffffffffu, ei, o);
        if (ov > v || (ov == v && oi < ei)) { v = ov; ei = oi; }
    }
    const int i1 = ei;

    const float c0 = (i0 < 32) ? p0 : p1;
    const float pi0 = __shfl_sync(0xffffffffu, c0, i0 & 31);
    const float c1 = (i1 < 32) ? p0 : p1;
    const float pi1 = __shfl_sync(0xffffffffu, c1, i1 & 31);

    if (lane == 0) {
        const float s0 = (1.0f - pi0) + pi0;
        const float s1 = (1.0f - pi1) + pi1;
        const float sn = fmaxf(s0 + s1, 1e-9f);
        out[OFF_IDX + t * 2 + 0]    = (float)i0;
        out[OFF_IDX + t * 2 + 1]    = (float)i1;
        out[OFF_SCORES + t * 2 + 0] = s0 / sn;
        out[OFF_SCORES + t * 2 + 1] = s1 / sn;
        atomicAdd(&s_load[i0], 1.f);
        atomicAdd(&s_load[i1], 1.f);
    }
    __syncthreads();
    if (tid < NEXP)
        atomicAdd(&out[OFF_IMP + tid], s_imp[tid] * (1.f / BS_TOK));
    else if (tid < 2 * NEXP)
        atomicAdd(&out[OFF_LOAD + tid - NEXP], s_load[tid - NEXP] * (1.f / BS_TOK));
}

// ---------------------------------------------------------------------------
// kernel_launch: graph-capturable sequence.
// Inputs: x[B,S,D], Wg[E,D], gamma[D], beta[D], W1[H,D], W2[1,H] (fp32)
// ---------------------------------------------------------------------------
extern "C" void kernel_launch(void* const* d_in, const int* in_sizes, int n_in,
                              void* d_out, int out_size) {
    const float* x     = (const float*)d_in[0];
    const float* Wg    = (const float*)d_in[1];
    const float* gamma = (const float*)d_in[2];
    const float* beta  = (const float*)d_in[3];
    const float* W1    = (const float*)d_in[4];
    const float* W2    = (const float*)d_in[5];
    float* out = (float*)d_out;

    cudaFuncSetAttribute(h1z_kernel, cudaFuncAttributeMaxDynamicSharedMemorySize, 102400);
    cudaFuncSetAttribute(logits_mma_kernel, cudaFuncAttributeMaxDynamicSharedMemorySize, 148480);

    // 1) stats + fp16 x split + zero accumulators
    prep_kernel<<<BS_TOK, 256>>>(x, out);
    // 2) weight conversions + LN affine constants
    w1conv_kernel<<<(HID * DIM / 4) / 256, 256>>>(W1, gamma);
    wgsplit_kernel<<<(NEXP * DIM) / 256, 256>>>(Wg);
    cvec_kernel<<<HID, 256>>>(W1, gamma, beta);
    // 3) logits via 3xfp16 split MMA
    logits_mma_kernel<<<BS_TOK / 128, 256, 148480>>>();
    // 4) fp16 mma h1 GEMM (raw x) + exact LN affine + GELU + W2-dot
    h1z_kernel<<<dim3(NXT, BS_TOK / 128), 256, 102400>>>(W2);
    // 5) softmax / top-2 / outputs
    epilogue_kernel<<<BS_TOK / 8, 256>>>(out);

    (void)in_sizes; (void)n_in; (void)out_size;
}

// round 15
// speedup vs baseline: 9.9515x; 1.0831x over previous
#include <cuda_runtime.h>
#include <cuda_fp16.h>
#include <math.h>
#include <stdint.h>

// Problem constants (fixed by setup_inputs)
#define BS_TOK 16384   // B*S
#define DIM    2048    // D
#define NEXP   64      // E
#define HID    1024    // D/2
#define NXT    (HID / 128)   // 8 N-tiles in the h1 GEMM

// Output layout (flattened tuple, fp32):
// idx[BS,2] | scores[BS,2] | probs_soft[BS,64] | importance[64] | load[64]
#define OFF_IDX    0
#define OFF_SCORES (BS_TOK * 2)
#define OFF_PROBS  (BS_TOK * 4)
#define OFF_IMP    (BS_TOK * 4 + BS_TOK * NEXP)
#define OFF_LOAD   (OFF_IMP + NEXP)

// Scratch (device globals: allocation-free)
__device__ __half g_xhi[(size_t)BS_TOK * DIM];          // fp16 hi of 1024*x
__device__ __half g_xlo[(size_t)BS_TOK * DIM];          // fp16 lo of 1024*x
__device__ __half g_w1h[(size_t)HID * DIM];             // fp16 of W1*gamma
__device__ __half g_wghi[(size_t)NEXP * DIM];           // fp16 hi of 1024*Wg
__device__ __half g_wglo[(size_t)NEXP * DIM];           // fp16 lo of 1024*Wg
__device__ float g_c1[HID];                             // sum_d gamma_d*W1[h,d]
__device__ float g_c2[HID];                             // sum_d beta_d*W1[h,d]
__device__ float g_mu[BS_TOK];
__device__ float g_rstd[BS_TOK];
__device__ float g_logits[(size_t)BS_TOK * NEXP];
__device__ float g_zpart[NXT][BS_TOK];

// ---------------------------------------------------------------------------
// PTX helpers — family-portable only (no tcgen05: ptxas targets sm_103 base)
// ---------------------------------------------------------------------------
__device__ __forceinline__ uint32_t smem_u32(const void* p) {
    uint32_t a;
    asm("{ .reg .u64 t; cvta.to.shared.u64 t, %1; cvt.u32.u64 %0, t; }" : "=r"(a) : "l"(p));
    return a;
}
#define SWZ(o) ((o) ^ (((o) >> 3) & 0x70))
#define CP_ASYNC16(dst, src) \
    asm volatile("cp.async.cg.shared.global [%0], [%1], 16;" :: "r"(dst), "l"(src))
#define CP_COMMIT() asm volatile("cp.async.commit_group;" ::: "memory")
#define CP_WAIT1()  asm volatile("cp.async.wait_group 1;" ::: "memory")
#define CP_WAIT0()  asm volatile("cp.async.wait_group 0;" ::: "memory")

__device__ __forceinline__ void ldsm4(uint32_t* r, uint32_t addr) {
    asm volatile("ldmatrix.sync.aligned.m8n8.x4.shared.b16 {%0,%1,%2,%3}, [%4];"
                 : "=r"(r[0]), "=r"(r[1]), "=r"(r[2]), "=r"(r[3]) : "r"(addr));
}
__device__ __forceinline__ void mma_f16(float* c, const uint32_t* a, const uint32_t* b) {
    asm volatile(
        "mma.sync.aligned.m16n8k16.row.col.f32.f16.f16.f32 "
        "{%0,%1,%2,%3}, {%4,%5,%6,%7}, {%8,%9}, {%0,%1,%2,%3};"
        : "+f"(c[0]), "+f"(c[1]), "+f"(c[2]), "+f"(c[3])
        : "r"(a[0]), "r"(a[1]), "r"(a[2]), "r"(a[3]), "r"(b[0]), "r"(b[1]));
}

// ---------------------------------------------------------------------------
// Kernel 1: per-token stats (mu, rstd) + fp16 hi/lo split of 1024*x.
// One pass: thread i handles elements [8i, 8i+8); uint4 (16B) stores.
// Zeroes importance/load accumulators (required every graph replay).
// ---------------------------------------------------------------------------
__global__ void __launch_bounds__(256) prep_kernel(
    const float* __restrict__ x, float* __restrict__ out) {
    const int t = blockIdx.x, tid = threadIdx.x;
    const float4* xr = reinterpret_cast<const float4*>(x + (size_t)t * DIM);

    const float4 va = xr[2 * tid], vb = xr[2 * tid + 1];
    float f[8] = {va.x, va.y, va.z, va.w, vb.x, vb.y, vb.z, vb.w};

    float s = 0.f, sq = 0.f;
    #pragma unroll
    for (int j = 0; j < 8; j++) { s += f[j]; sq += f[j] * f[j]; }
    __shared__ float rs_[8], rq_[8];
    #pragma unroll
    for (int o = 16; o; o >>= 1) {
        s  += __shfl_down_sync(0xffffffffu, s, o);
        sq += __shfl_down_sync(0xffffffffu, sq, o);
    }
    if ((tid & 31) == 0) { rs_[tid >> 5] = s; rq_[tid >> 5] = sq; }
    __syncthreads();
    if (tid == 0) {
        float S = 0.f, Q = 0.f;
        #pragma unroll
        for (int i = 0; i < 8; i++) { S += rs_[i]; Q += rq_[i]; }
        float mu  = S * (1.f / DIM);
        float var = Q * (1.f / DIM) - mu * mu;
        g_mu[t]   = mu;
        g_rstd[t] = rsqrtf(var + 1e-5f);
    }
    __half hi[8], lo[8];
    #pragma unroll
    for (int j = 0; j < 8; j++) {
        float g = f[j] * 1024.f;
        hi[j] = __float2half_rn(g);
        lo[j] = __float2half_rn(g - __half2float(hi[j]));
    }
    uint4 uh, ul;
    {
        __half2 a0 = __halves2half2(hi[0], hi[1]), a1 = __halves2half2(hi[2], hi[3]);
        __half2 a2 = __halves2half2(hi[4], hi[5]), a3 = __halves2half2(hi[6], hi[7]);
        uh.x = *reinterpret_cast<unsigned int*>(&a0);
        uh.y = *reinterpret_cast<unsigned int*>(&a1);
        uh.z = *reinterpret_cast<unsigned int*>(&a2);
        uh.w = *reinterpret_cast<unsigned int*>(&a3);
        __half2 b0 = __halves2half2(lo[0], lo[1]), b1 = __halves2half2(lo[2], lo[3]);
        __half2 b2 = __halves2half2(lo[4], lo[5]), b3 = __halves2half2(lo[6], lo[7]);
        ul.x = *reinterpret_cast<unsigned int*>(&b0);
        ul.y = *reinterpret_cast<unsigned int*>(&b1);
        ul.z = *reinterpret_cast<unsigned int*>(&b2);
        ul.w = *reinterpret_cast<unsigned int*>(&b3);
    }
    reinterpret_cast<uint4*>(g_xhi + (size_t)t * DIM)[tid] = uh;
    reinterpret_cast<uint4*>(g_xlo + (size_t)t * DIM)[tid] = ul;
    if (blockIdx.x == 0 && tid < 2 * NEXP) out[OFF_IMP + tid] = 0.f;
}

// ---------------------------------------------------------------------------
// Kernel 2a: W1*gamma -> fp16.  2b: Wg -> fp16 hi/lo (scaled 1024).
// 2c: c1[h] = sum_d gamma_d W1[h,d], c2[h] = sum_d beta_d W1[h,d].
// ---------------------------------------------------------------------------
__global__ void __launch_bounds__(256) w1conv_kernel(
    const float* __restrict__ W1, const float* __restrict__ gamma) {
    size_t i = (size_t)blockIdx.x * 256 + threadIdx.x;
    float4 v = reinterpret_cast<const float4*>(W1)[i];
    float4 g = reinterpret_cast<const float4*>(gamma)[i % (DIM / 4)];
    __half2 pa = __floats2half2_rn(v.x * g.x, v.y * g.y);
    __half2 pb = __floats2half2_rn(v.z * g.z, v.w * g.w);
    uint2 u;
    u.x = *reinterpret_cast<unsigned int*>(&pa);
    u.y = *reinterpret_cast<unsigned int*>(&pb);
    reinterpret_cast<uint2*>(g_w1h)[i] = u;
}
__global__ void __launch_bounds__(256) wgsplit_kernel(const float* __restrict__ Wg) {
    size_t i = (size_t)blockIdx.x * 256 + threadIdx.x;
    float w = Wg[i] * 1024.f;
    __half hi = __float2half_rn(w);
    __half lo = __float2half_rn(w - __half2float(hi));
    g_wghi[i] = hi; g_wglo[i] = lo;
}
__global__ void __launch_bounds__(256) cvec_kernel(
    const float* __restrict__ W1, const float* __restrict__ gamma,
    const float* __restrict__ beta) {
    const int h = blockIdx.x, tid = threadIdx.x;
    const float4* wr = reinterpret_cast<const float4*>(W1 + (size_t)h * DIM);
    const float4* gr = reinterpret_cast<const float4*>(gamma);
    const float4* br = reinterpret_cast<const float4*>(beta);
    float c1 = 0.f, c2 = 0.f;
    #pragma unroll 2
    for (int i = tid; i < DIM / 4; i += 256) {
        float4 w = wr[i], g = gr[i], b = br[i];
        c1 += w.x * g.x + w.y * g.y + w.z * g.z + w.w * g.w;
        c2 += w.x * b.x + w.y * b.y + w.z * b.z + w.w * b.w;
    }
    __shared__ float r1[8], r2[8];
    #pragma unroll
    for (int o = 16; o; o >>= 1) {
        c1 += __shfl_down_sync(0xffffffffu, c1, o);
        c2 += __shfl_down_sync(0xffffffffu, c2, o);
    }
    if ((tid & 31) == 0) { r1[tid >> 5] = c1; r2[tid >> 5] = c2; }
    __syncthreads();
    if (tid == 0) {
        float a = 0.f, b = 0.f;
        #pragma unroll
        for (int i = 0; i < 8; i++) { a += r1[i]; b += r2[i]; }
        g_c1[h] = a; g_c2[h] = b;
    }
}

// ---------------------------------------------------------------------------
// Kernel 3: logits = x @ Wg^T via 3xfp16 split MMA (unchanged, verified R9+).
// ---------------------------------------------------------------------------
__device__ __forceinline__ void copy_stageL(uint32_t st, const char* ahi, const char* alo,
                                            const char* bhi, const char* blo,
                                            int tid, size_t koff) {
    #pragma unroll
    for (int t = 0; t < 4; t++) {   // A: 128 rows x 8 units
        int u = tid + t * 256;
        int row = u >> 3, cu = u & 7;
        size_t g = (size_t)row * (DIM * 2) + koff + (size_t)cu * 16;
        uint32_t so = SWZ(row * 128 + cu * 16);
        CP_ASYNC16(st + so, ahi + g);
        CP_ASYNC16(st + 16384 + so, alo + g);
    }
    #pragma unroll
    for (int t = 0; t < 2; t++) {   // B: 64 rows x 8 units
        int u = tid + t * 256;
        int row = u >> 3, cu = u & 7;
        size_t g = (size_t)row * (DIM * 2) + koff + (size_t)cu * 16;
        uint32_t so = SWZ(row * 128 + cu * 16);
        CP_ASYNC16(st + 32768 + so, bhi + g);
        CP_ASYNC16(st + 40960 + so, blo + g);
    }
}

__global__ void __launch_bounds__(256, 1) logits_mma_kernel() {
    extern __shared__ char dynsmem[];
    const uint32_t raw  = smem_u32(dynsmem);
    const uint32_t base = (raw + 1023u) & ~1023u;

    const int tid = threadIdx.x, wid = tid >> 5, lane = tid & 31;
    const int warp_m = wid >> 1, warp_n = wid & 1;
    const int bm = blockIdx.x * 128;

    const char* ahi = reinterpret_cast<const char*>(g_xhi + (size_t)bm * DIM);
    const char* alo = reinterpret_cast<const char*>(g_xlo + (size_t)bm * DIM);
    const char* bhi = reinterpret_cast<const char*>(g_wghi);
    const char* blo = reinterpret_cast<const char*>(g_wglo);

    copy_stageL(base, ahi, alo, bhi, blo, tid, 0);           CP_COMMIT();
    copy_stageL(base + 49152, ahi, alo, bhi, blo, tid, 128); CP_COMMIT();

    float acc[2][4][4];
    #pragma unroll
    for (int a = 0; a < 2; a++)
        #pragma unroll
        for (int b = 0; b < 4; b++)
            #pragma unroll
            for (int c = 0; c < 4; c++) acc[a][b][c] = 0.f;

    #pragma unroll 1
    for (int i = 0; i < 32; i++) {
        if (i == 31) { CP_WAIT0(); } else { CP_WAIT1(); }
        __syncthreads();
        if (i + 2 < 32) {
            copy_stageL(base + ((i + 2) % 3) * 49152, ahi, alo, bhi, blo,
                        tid, (size_t)(i + 2) * 128);
            CP_COMMIT();
        }
        const uint32_t sA  = base + (i % 3) * 49152;
        const uint32_t sAl = sA + 16384;
        const uint32_t sB  = sA + 32768;
        const uint32_t sBl = sA + 40960;
        #pragma unroll
        for (int ks = 0; ks < 4; ks++) {
            uint32_t rah[2][4], ral[2][4];
            #pragma unroll
            for (int a = 0; a < 2; a++) {
                int row = warp_m * 32 + a * 16 + (lane & 15);
                int bc  = ks * 32 + (((lane >> 4) & 1) << 4);
                ldsm4(rah[a], sA + SWZ(row * 128 + bc));
                ldsm4(ral[a], sAl + SWZ(row * 128 + bc));
            }
            uint32_t rbh[4][2], rbl[4][2];
            #pragma unroll
            for (int bb = 0; bb < 4; bb += 2) {
                int nrow = warp_n * 32 + bb * 8 + (lane & 7) + ((lane >> 4) & 1) * 8;
                int kc   = ks * 32 + (((lane >> 3) & 1) << 4);
                uint32_t r[4];
                ldsm4(r, sB + SWZ(nrow * 128 + kc));
                rbh[bb][0] = r[0]; rbh[bb][1] = r[1];
                rbh[bb + 1][0] = r[2]; rbh[bb + 1][1] = r[3];
                ldsm4(r, sBl + SWZ(nrow * 128 + kc));
                rbl[bb][0] = r[0]; rbl[bb][1] = r[1];
                rbl[bb + 1][0] = r[2]; rbl[bb + 1][1] = r[3];
            }
            #pragma unroll
            for (int a = 0; a < 2; a++)
                #pragma unroll
                for (int b = 0; b < 4; b++) {
                    mma_f16(acc[a][b], rah[a], rbh[b]);
                    mma_f16(acc[a][b], rah[a], rbl[b]);
                    mma_f16(acc[a][b], ral[a], rbh[b]);
                }
        }
    }

    const float SC = 1.f / 1048576.f;   // 2^-20 (1024 * 1024 operand scaling)
    #pragma unroll
    for (int a = 0; a < 2; a++) {
        const int row = bm + warp_m * 32 + a * 16 + (lane >> 2);
        #pragma unroll
        for (int b = 0; b < 4; b++) {
            const int col = warp_n * 32 + b * 8 + 2 * (lane & 3);
            g_logits[(size_t)row * NEXP + col]           = acc[a][b][0] * SC;
            g_logits[(size_t)row * NEXP + col + 1]       = acc[a][b][1] * SC;
            g_logits[(size_t)(row + 8) * NEXP + col]     = acc[a][b][2] * SC;
            g_logits[(size_t)(row + 8) * NEXP + col + 1] = acc[a][b][3] * SC;
        }
    }
}

// ---------------------------------------------------------------------------
// Kernel 4: fp16 mma GEMM acc = (1024*x) @ (W1*gamma)^T, CTA 128x128.
// BK=128 chunks (two 64-col halves, same verified layout), 3 stages of 64KB,
// ONE sync per chunk (16 total). Epilogue: exact LN affine + GELU + W2-dot.
// ---------------------------------------------------------------------------
__device__ __forceinline__ void copy_stageH(uint32_t st, const char* ag, const char* bg,
                                            int tid, size_t kbytes) {
    #pragma unroll
    for (int h = 0; h < 2; h++) {
        #pragma unroll
        for (int t4 = 0; t4 < 4; t4++) {
            int u = tid + t4 * 256;
            int row = u >> 3, cu = u & 7;
            size_t g = (size_t)row * (DIM * 2) + kbytes + (size_t)h * 128 + (size_t)cu * 16;
            uint32_t so = SWZ(row * 128 + cu * 16);
            CP_ASYNC16(st + h * 16384 + so, ag + g);
            CP_ASYNC16(st + 32768 + h * 16384 + so, bg + g);
        }
    }
}

__device__ __forceinline__ void compute_chunk(uint32_t abase, uint32_t bbase,
                                              int warp_m, int warp_n, int lane,
                                              float acc[4][4][4]) {
    #pragma unroll
    for (int ks = 0; ks < 4; ks++) {
        uint32_t ra[4][4];
        #pragma unroll
        for (int a = 0; a < 4; a++) {
            int row = warp_m * 64 + a * 16 + (lane & 15);
            int bc  = ks * 32 + (((lane >> 4) & 1) << 4);
            ldsm4(ra[a], abase + SWZ(row * 128 + bc));
        }
        uint32_t rb[4][2];
        #pragma unroll
        for (int bb = 0; bb < 4; bb += 2) {
            int nrow = warp_n * 32 + bb * 8 + (lane & 7) + ((lane >> 4) & 1) * 8;
            int kc   = ks * 32 + (((lane >> 3) & 1) << 4);
            uint32_t r[4];
            ldsm4(r, bbase + SWZ(nrow * 128 + kc));
            rb[bb][0] = r[0];     rb[bb][1] = r[1];
            rb[bb + 1][0] = r[2]; rb[bb + 1][1] = r[3];
        }
        #pragma unroll
        for (int a = 0; a < 4; a++)
            #pragma unroll
            for (int b = 0; b < 4; b++)
                mma_f16(acc[a][b], ra[a], rb[b]);
    }
}

__global__ void __launch_bounds__(256, 1) h1z_kernel(const float* __restrict__ W2) {
    extern __shared__ char dynsmem[];
    const uint32_t raw  = smem_u32(dynsmem);
    const uint32_t base = (raw + 1023u) & ~1023u;
    char* sm = dynsmem + (base - raw);
    const int OW2 = 196608, OZ = 197120, OC1 = 197632, OC2 = 198144;
    const int OMU = 198656, ORS = 199168;

    const int tid = threadIdx.x, wid = tid >> 5, lane = tid & 31;
    const int warp_m = wid >> 2, warp_n = wid & 3;
    const int bn = blockIdx.x * 128;
    const int bm = blockIdx.y * 128;

    float* w2s  = reinterpret_cast<float*>(sm + OW2);
    float* zrow = reinterpret_cast<float*>(sm + OZ);
    float* sc1  = reinterpret_cast<float*>(sm + OC1);
    float* sc2  = reinterpret_cast<float*>(sm + OC2);
    float* smu  = reinterpret_cast<float*>(sm + OMU);
    float* srs  = reinterpret_cast<float*>(sm + ORS);
    if (tid < 128) {
        w2s[tid] = W2[bn + tid];
        zrow[tid] = 0.f;
        sc1[tid] = g_c1[bn + tid];
        sc2[tid] = g_c2[bn + tid];
        smu[tid] = g_mu[bm + tid];
        srs[tid] = g_rstd[bm + tid];
    }

    const char* ag = reinterpret_cast<const char*>(g_xhi + (size_t)bm * DIM);
    const char* bg = reinterpret_cast<const char*>(g_w1h + (size_t)bn * DIM);

    copy_stageH(base, ag, bg, tid, 0);           CP_COMMIT();
    copy_stageH(base + 65536, ag, bg, tid, 256); CP_COMMIT();

    float acc[4][4][4];
    #pragma unroll
    for (int a = 0; a < 4; a++)
        #pragma unroll
        for (int b = 0; b < 4; b++)
            #pragma unroll
            for (int c = 0; c < 4; c++) acc[a][b][c] = 0.f;

    #pragma unroll 1
    for (int i = 0; i < 16; i++) {
        if (i == 15) { CP_WAIT0(); } else { CP_WAIT1(); }
        __syncthreads();
        if (i + 2 < 16) {
            copy_stageH(base + ((i + 2) % 3) * 65536, ag, bg, tid, (size_t)(i + 2) * 256);
            CP_COMMIT();
        }
        const uint32_t st = base + (i % 3) * 65536;
        compute_chunk(st, st + 32768, warp_m, warp_n, lane, acc);          // half 0
        compute_chunk(st + 16384, st + 49152, warp_m, warp_n, lane, acc);  // half 1
    }

    // Fused epilogue: exact LN affine + GELU + dot with W2, row-reduce.
    float z[8];
    #pragma unroll
    for (int j = 0; j < 8; j++) z[j] = 0.f;
    #pragma unroll
    for (int a = 0; a < 4; a++) {
        const int r0 = warp_m * 64 + a * 16 + (lane >> 2);
        const float rs0 = srs[r0], mu0 = smu[r0];
        const float rs1 = srs[r0 + 8], mu1 = smu[r0 + 8];
        #pragma unroll
        for (int b = 0; b < 4; b++) {
            const int colb = warp_n * 32 + b * 8 + 2 * (lane & 3);
            const float w0 = w2s[colb], w1 = w2s[colb + 1];
            const float c10 = sc1[colb], c11 = sc1[colb + 1];
            const float c20 = sc2[colb], c21 = sc2[colb + 1];
            float v0 = rs0 * (acc[a][b][0] * (1.f / 1024.f) - mu0 * c10) + c20;
            float v1 = rs0 * (acc[a][b][1] * (1.f / 1024.f) - mu0 * c11) + c21;
            float v2 = rs1 * (acc[a][b][2] * (1.f / 1024.f) - mu1 * c10) + c20;
            float v3 = rs1 * (acc[a][b][3] * (1.f / 1024.f) - mu1 * c11) + c21;
            v0 = 0.5f * v0 * (1.f + erff(v0 * 0.70710678118654752f));
            v1 = 0.5f * v1 * (1.f + erff(v1 * 0.70710678118654752f));
            v2 = 0.5f * v2 * (1.f + erff(v2 * 0.70710678118654752f));
            v3 = 0.5f * v3 * (1.f + erff(v3 * 0.70710678118654752f));
            z[a * 2 + 0] += v0 * w0 + v1 * w1;
            z[a * 2 + 1] += v2 * w0 + v3 * w1;
        }
    }
    #pragma unroll
    for (int m = 1; m <= 2; m <<= 1)
        #pragma unroll
        for (int j = 0; j < 8; j++)
            z[j] += __shfl_xor_sync(0xffffffffu, z[j], m);
    if ((lane & 3) == 0) {
        #pragma unroll
        for (int a = 0; a < 4; a++) {
            const int r0 = warp_m * 64 + a * 16 + (lane >> 2);
            atomicAdd(&zrow[r0], z[a * 2 + 0]);
            atomicAdd(&zrow[r0 + 8], z[a * 2 + 1]);
        }
    }
    __syncthreads();
    if (tid < 128) g_zpart[blockIdx.x][bm + tid] = zrow[tid];
}

// ---------------------------------------------------------------------------
// Kernel 5: epilogue, 4 tokens per warp (32/block, grid 512).
// ---------------------------------------------------------------------------
__global__ void __launch_bounds__(256) epilogue_kernel(float* __restrict__ out) {
    __shared__ float s_imp[NEXP], s_load[NEXP];
    const int tid = threadIdx.x;
    if (tid < NEXP) s_imp[tid] = 0.f;
    else if (tid < 2 * NEXP) s_load[tid - NEXP] = 0.f;
    __syncthreads();

    const int w = tid >> 5, lane = tid & 31;
    float impacc0 = 0.f, impacc1 = 0.f;

    #pragma unroll 1
    for (int j = 0; j < 4; j++) {
        const int t = blockIdx.x * 32 + w * 4 + j;

        float zp = (lane < NXT) ? g_zpart[lane][t] : 0.f;
        #pragma unroll
        for (int o = 16; o; o >>= 1) zp += __shfl_xor_sync(0xffffffffu, zp, o);
        const float sc = 1.f / (1.f + 1.f / (1.f + expf(-zp)));

        const float* lrow = g_logits + (size_t)t * NEXP;
        const float l0 = lrow[lane] * sc;
        const float l1 = lrow[lane + 32] * sc;

        float m = fmaxf(l0, l1);
        #pragma unroll
        for (int o = 16; o; o >>= 1) m = fmaxf(m, __shfl_xor_sync(0xffffffffu, m, o));
        const float e0 = expf(l0 - m), e1 = expf(l1 - m);
        float se = e0 + e1;
        #pragma unroll
        for (int o = 16; o; o >>= 1) se += __shfl_xor_sync(0xffffffffu, se, o);
        const float inv = 1.f / se;
        const float p0 = e0 * inv, p1 = e1 * inv;

        out[OFF_PROBS + (size_t)t * NEXP + lane]      = p0;
        out[OFF_PROBS + (size_t)t * NEXP + lane + 32] = p1;
        impacc0 += p0;
        impacc1 += p1;

        float v; int ei;
        if (l1 > l0) { v = l1; ei = lane + 32; } else { v = l0; ei = lane; }
        #pragma unroll
        for (int o = 16; o; o >>= 1) {
            float ov = __shfl_xor_sync(0xffffffffu, v, o);
            int   oi = __shfl_xor_sync(0xffffffffu, ei, o);
            if (ov > v || (ov == v && oi < ei)) { v = ov; ei = oi; }
        }
        const int i0 = ei;
        float a0 = (lane == i0)      ? -3.4e38f : l0;
        float a1 = (lane + 32 == i0) ? -3.4e38f : l1;
        if (a1 > a0) { v = a1; ei = lane + 32; } else { v = a0; ei = lane; }
        #pragma unroll
        for (int o = 16; o; o >>= 1) {
            float ov = __shfl_xor_sync(0xffffffffu, v, o);
            int   oi = __shfl_xor_sync(0xffffffffu, ei, o);
            if (ov > v || (ov == v && oi < ei)) { v = ov; ei = oi; }
        }
        const int i1 = ei;

        const float c0 = (i0 < 32) ? p0 : p1;
        const float pi0 = __shfl_sync(0xffffffffu, c0, i0 & 31);
        const float c1 = (i1 < 32) ? p0 : p1;
        const float pi1 = __shfl_sync(0xffffffffu, c1, i1 & 31);

        if (lane == 0) {
            const float s0 = (1.0f - pi0) + pi0;
            const float s1 = (1.0f - pi1) + pi1;
            const float sn = fmaxf(s0 + s1, 1e-9f);
            out[OFF_IDX + t * 2 + 0]    = (float)i0;
            out[OFF_IDX + t * 2 + 1]    = (float)i1;
            out[OFF_SCORES + t * 2 + 0] = s0 / sn;
            out[OFF_SCORES + t * 2 + 1] = s1 / sn;
            atomicAdd(&s_load[i0], 1.f);
            atomicAdd(&s_load[i1], 1.f);
        }
    }
    atomicAdd(&s_imp[lane], impacc0);
    atomicAdd(&s_imp[lane + 32], impacc1);
    __syncthreads();
    if (tid < NEXP)
        atomicAdd(&out[OFF_IMP + tid], s_imp[tid] * (1.f / BS_TOK));
    else if (tid < 2 * NEXP)
        atomicAdd(&out[OFF_LOAD + tid - NEXP], s_load[tid - NEXP] * (1.f / BS_TOK));
}

// ---------------------------------------------------------------------------
// kernel_launch: graph-capturable sequence.
// Inputs: x[B,S,D], Wg[E,D], gamma[D], beta[D], W1[H,D], W2[1,H] (fp32)
// ---------------------------------------------------------------------------
extern "C" void kernel_launch(void* const* d_in, const int* in_sizes, int n_in,
                              void* d_out, int out_size) {
    const float* x     = (const float*)d_in[0];
    const float* Wg    = (const float*)d_in[1];
    const float* gamma = (const float*)d_in[2];
    const float* beta  = (const float*)d_in[3];
    const float* W1    = (const float*)d_in[4];
    const float* W2    = (const float*)d_in[5];
    float* out = (float*)d_out;

    cudaFuncSetAttribute(h1z_kernel, cudaFuncAttributeMaxDynamicSharedMemorySize, 200704);
    cudaFuncSetAttribute(logits_mma_kernel, cudaFuncAttributeMaxDynamicSharedMemorySize, 148480);

    // 1) stats + fp16 x split + zero accumulators
    prep_kernel<<<BS_TOK, 256>>>(x, out);
    // 2) weight conversions + LN affine constants
    w1conv_kernel<<<(HID * DIM / 4) / 256, 256>>>(W1, gamma);
    wgsplit_kernel<<<(NEXP * DIM) / 256, 256>>>(Wg);
    cvec_kernel<<<HID, 256>>>(W1, gamma, beta);
    // 3) logits via 3xfp16 split MMA
    logits_mma_kernel<<<BS_TOK / 128, 256, 148480>>>();
    // 4) fp16 mma h1 GEMM (BK=128, 3-stage) + exact LN affine + GELU + W2-dot
    h1z_kernel<<<dim3(NXT, BS_TOK / 128), 256, 200704>>>(W2);
    // 5) softmax / top-2 / outputs
    epilogue_kernel<<<BS_TOK / 32, 256>>>(out);

    (void)in_sizes; (void)n_in; (void)out_size;
}